// round 13
// baseline (speedup 1.0000x reference)
#include <cuda_runtime.h>
#include <cuda_fp16.h>
#include <cstdint>
#include <math.h>

#define TOTAL_ATOMS 65536
#define NUM_GRAPHS  512
#define DMODEL      256
#define NHEAD       4
#define DHEAD       64
#define NMAX        160

// ---------------- scratch ----------------
__device__ __half g_qkv [ (size_t)TOTAL_ATOMS * 3 * DMODEL ];
__device__ __half g_bufA[ (size_t)TOTAL_ATOMS * DMODEL ];
__device__ __half g_bufB[ (size_t)TOTAL_ATOMS * DMODEL ];
__device__ __half g_xh  [ (size_t)TOTAL_ATOMS * DMODEL ];
__device__ __half g_w1h [ 3 * DMODEL * DMODEL ];
__device__ __half g_w2h [ 3 * DMODEL * DMODEL ];
__device__ __half g_ow2h[ DMODEL * DMODEL ];
__device__ __half g_wo1t[ DMODEL * DMODEL ];          // Wo1^T fp16
__device__ __half g_wcomb[ 3 * DMODEL * DMODEL ];     // Wi2 @ Wo1 fp16
__device__ float  g_bcomb[ 3 * DMODEL ];              // Wi2 @ bo1 + bi2
__device__ float  g_zero256[ DMODEL ];                // zero-initialized
__device__ float g_pooled[ NUM_GRAPHS * DMODEL ];
__device__ float g_r1    [ NUM_GRAPHS * DMODEL ];
__device__ float g_r2    [ NUM_GRAPHS * 128 ];
__device__ int   g_start [ NUM_GRAPHS + 1 ];

// ---------------- per-graph start offsets ----------------
__global__ void compute_starts_kernel(const int* __restrict__ batch) {
    int i = blockIdx.x * blockDim.x + threadIdx.x;
    if (i >= TOTAL_ATOMS) return;
    if (i == 0) {
        g_start[batch[0]] = 0;
        g_start[NUM_GRAPHS] = TOTAL_ATOMS;
    } else if (batch[i] != batch[i - 1]) {
        g_start[batch[i]] = i;
    }
}

// ---------------- fused fp32 -> fp16 convert (x + 3 weight blocks) --------
#define NX4 (TOTAL_ATOMS * DMODEL / 4)
#define NW4 (3 * DMODEL * DMODEL / 4)
#define NO4 (DMODEL * DMODEL / 4)
__global__ void f2h_all_kernel(const float* __restrict__ x,
                               const float* __restrict__ w1,
                               const float* __restrict__ w2, const float* __restrict__ ow2,
                               __half* __restrict__ xh,
                               __half* __restrict__ w1h,
                               __half* __restrict__ w2h, __half* __restrict__ ow2h) {
    int i = blockIdx.x * blockDim.x + threadIdx.x;
    const float* src;
    __half* dst;
    int off;
    if (i < NX4)                          { src = x;   dst = xh;   off = i; }
    else if (i < NX4 + NW4)               { src = w1;  dst = w1h;  off = i - NX4; }
    else if (i < NX4 + 2 * NW4)           { src = w2;  dst = w2h;  off = i - NX4 - NW4; }
    else if (i < NX4 + 2 * NW4 + NO4)     { src = ow2; dst = ow2h; off = i - NX4 - 2 * NW4; }
    else return;
    float4 v = ((const float4*)src)[off];
    __half2* d = (__half2*)dst + off * 2;
    d[0] = __floats2half2_rn(v.x, v.y);
    d[1] = __floats2half2_rn(v.z, v.w);
}

// ---------------- transpose-convert: dst[j][k] = half(src[k][j]), 256x256 --
__global__ void transpose_h_kernel(const float* __restrict__ src, __half* __restrict__ dst) {
    __shared__ float tile[32][33];
    int bx = blockIdx.x * 32, by = blockIdx.y * 32;
    tile[threadIdx.y][threadIdx.x] = src[(by + threadIdx.y) * DMODEL + bx + threadIdx.x];
    __syncthreads();
    dst[(bx + threadIdx.y) * DMODEL + by + threadIdx.x] =
        __float2half(tile[threadIdx.x][threadIdx.y]);
}

// ---------------- bcomb[i] = dot(Wi2[i,:], bo1) + bi2[i] ----------------
__global__ void bcomb_kernel(const float* __restrict__ w2, const float* __restrict__ bo1,
                             const float* __restrict__ bi2, float* __restrict__ bcomb) {
    int i = blockIdx.x * blockDim.x + threadIdx.x;   // 768
    float s = bi2[i];
    for (int k = 0; k < DMODEL; k++) s += w2[i * DMODEL + k] * bo1[k];
    bcomb[i] = s;
}

// ---------------- asm helpers ----------------
__device__ __forceinline__ uint32_t smem_u32(const void* p) {
    uint32_t a;
    asm("{ .reg .u64 t; cvta.to.shared.u64 t, %1; cvt.u32.u64 %0, t; }" : "=r"(a) : "l"(p));
    return a;
}
__device__ __forceinline__ void mma_f16(float* d, const uint32_t* a, const uint32_t* b) {
    asm volatile(
        "mma.sync.aligned.m16n8k16.row.col.f32.f16.f16.f32 "
        "{%0,%1,%2,%3}, {%4,%5,%6,%7}, {%8,%9}, {%0,%1,%2,%3};"
        : "+f"(d[0]), "+f"(d[1]), "+f"(d[2]), "+f"(d[3])
        : "r"(a[0]), "r"(a[1]), "r"(a[2]), "r"(a[3]), "r"(b[0]), "r"(b[1]));
}
#define LDSM_X4(r0, r1, r2, r3, addr) \
    asm volatile("ldmatrix.sync.aligned.m8n8.x4.shared.b16 {%0,%1,%2,%3}, [%4];" \
        : "=r"(r0), "=r"(r1), "=r"(r2), "=r"(r3) : "r"(addr))
#define LDSM_X2(r0, r1, addr) \
    asm volatile("ldmatrix.sync.aligned.m8n8.x2.shared.b16 {%0,%1}, [%2];" \
        : "=r"(r0), "=r"(r1) : "r"(addr))
#define CP_ASYNC16(dst, src) \
    asm volatile("cp.async.cg.shared.global [%0], [%1], 16;" :: "r"(dst), "l"(src))
#define CP_COMMIT() asm volatile("cp.async.commit_group;" ::: "memory")
#define CP_WAIT2()  asm volatile("cp.async.wait_group 2;" ::: "memory")

// ================= fp16 GEMM, 128x128 tile (R10 proven config) ============
#define STAGE_BYTES 20480
#define TCG_SMEM (4 * STAGE_BYTES)

__global__ void __launch_bounds__(256, 2)
h16_gemm_kernel(const __half* __restrict__ A, const __half* __restrict__ B,
                const float* __restrict__ bias, __half* __restrict__ C, int Ntot) {
    extern __shared__ char smem[];
    uint32_t sbase = smem_u32(smem);
    const int K = DMODEL;

    int tid   = threadIdx.x;
    int lane  = tid & 31;
    int wid   = tid >> 5;
    int warpM = wid & 1;
    int warpN = wid >> 1;
    int m0 = blockIdx.y * 128;
    int n0 = blockIdx.x * 128;

    const __half* Ab = A + (size_t)m0 * K;
    const __half* Bb = B + (size_t)n0 * K;

    int ar0 = tid >> 2;
    int aq  = tid & 3;
    int ar1 = ar0 + 64;
    uint32_t adst0 = ar0 * 80 + aq * 16;
    uint32_t adst1 = ar1 * 80 + aq * 16;
    const __half* asrc0 = Ab + (size_t)ar0 * K + aq * 8;
    const __half* asrc1 = Ab + (size_t)ar1 * K + aq * 8;
    const __half* bsrc0 = Bb + (size_t)ar0 * K + aq * 8;
    const __half* bsrc1 = Bb + (size_t)ar1 * K + aq * 8;

    int lr  = lane & 7;
    int seg = lane >> 3;
    uint32_t aoff = (uint32_t)((warpM * 64 + lr + (seg & 1) * 8) * 80 + (seg >> 1) * 16);
    uint32_t boff = (uint32_t)(10240 + (warpN * 32 + lr) * 80 + (seg & 1) * 16);

    float acc[4][4][4];
#pragma unroll
    for (int mt = 0; mt < 4; mt++)
#pragma unroll
        for (int nt = 0; nt < 4; nt++)
#pragma unroll
            for (int j = 0; j < 4; j++) acc[mt][nt][j] = 0.f;

#pragma unroll
    for (int s = 0; s < 3; s++) {
        uint32_t stg = sbase + s * STAGE_BYTES;
        int k0 = s * 32;
        CP_ASYNC16(stg + adst0,         asrc0 + k0);
        CP_ASYNC16(stg + adst1,         asrc1 + k0);
        CP_ASYNC16(stg + 10240 + adst0, bsrc0 + k0);
        CP_ASYNC16(stg + 10240 + adst1, bsrc1 + k0);
        CP_COMMIT();
    }

#pragma unroll 1
    for (int ch = 0; ch < 8; ch++) {
        CP_WAIT2();
        __syncthreads();

        if (ch + 3 < 8) {
            uint32_t stg = sbase + ((ch + 3) & 3) * STAGE_BYTES;
            int k0 = (ch + 3) * 32;
            CP_ASYNC16(stg + adst0,         asrc0 + k0);
            CP_ASYNC16(stg + adst1,         asrc1 + k0);
            CP_ASYNC16(stg + 10240 + adst0, bsrc0 + k0);
            CP_ASYNC16(stg + 10240 + adst1, bsrc1 + k0);
        }
        CP_COMMIT();

        uint32_t st = sbase + (ch & 3) * STAGE_BYTES;

#pragma unroll
        for (int ks = 0; ks < 2; ks++) {
            uint32_t af[4][4];
#pragma unroll
            for (int mt = 0; mt < 4; mt++)
                LDSM_X4(af[mt][0], af[mt][1], af[mt][2], af[mt][3],
                        st + aoff + mt * 1280 + ks * 32);
            uint32_t bf[4][2];
#pragma unroll
            for (int nt = 0; nt < 4; nt++)
                LDSM_X2(bf[nt][0], bf[nt][1],
                        st + boff + nt * 640 + ks * 32);
#pragma unroll
            for (int mt = 0; mt < 4; mt++)
#pragma unroll
                for (int nt = 0; nt < 4; nt++)
                    mma_f16(acc[mt][nt], af[mt], bf[nt]);
        }
    }

    int r  = lane >> 2;
    int c2 = (lane & 3) * 2;
#pragma unroll
    for (int nt = 0; nt < 4; nt++) {
        int col = n0 + warpN * 32 + nt * 8 + c2;
        float bx = bias[col], by = bias[col + 1];
#pragma unroll
        for (int mt = 0; mt < 4; mt++) {
            int row = m0 + warpM * 64 + mt * 16 + r;
            __half2* p0 = (__half2*)(C + (size_t)row * Ntot + col);
            __half2* p1 = (__half2*)(C + (size_t)(row + 8) * Ntot + col);
            *p0 = __floats2half2_rn(acc[mt][nt][0] + bx, acc[mt][nt][1] + by);
            *p1 = __floats2half2_rn(acc[mt][nt][2] + bx, acc[mt][nt][3] + by);
        }
    }
}

// ---------------- fp32 GEMM (small readout layers) ----------------
template <bool RELU>
__global__ void __launch_bounds__(256)
gemm_tn_kernel(const float* __restrict__ A, const float* __restrict__ B,
               const float* __restrict__ bias, float* __restrict__ C,
               int M, int N, int K) {
    const int BM = 128, BN = 128, BK = 8;
    __shared__ float As[BK][BM];
    __shared__ float Bs[BK][BN];

    int tid  = threadIdx.x;
    int brow = blockIdx.y;
    int bcol = blockIdx.x;

    const float* Ab = A + (size_t)brow * BM * K;
    const float* Bb = B + (size_t)bcol * BN * K;

    int lr = tid >> 1;
    int lc = (tid & 1) * 4;
    int ty = tid >> 4;
    int tx = tid & 15;

    float acc[8][8];
#pragma unroll
    for (int i = 0; i < 8; i++)
#pragma unroll
        for (int j = 0; j < 8; j++) acc[i][j] = 0.f;

    for (int k0 = 0; k0 < K; k0 += BK) {
        float4 a = *(const float4*)(Ab + (size_t)lr * K + k0 + lc);
        float4 b = *(const float4*)(Bb + (size_t)lr * K + k0 + lc);
        As[lc + 0][lr] = a.x; As[lc + 1][lr] = a.y;
        As[lc + 2][lr] = a.z; As[lc + 3][lr] = a.w;
        Bs[lc + 0][lr] = b.x; Bs[lc + 1][lr] = b.y;
        Bs[lc + 2][lr] = b.z; Bs[lc + 3][lr] = b.w;
        __syncthreads();
#pragma unroll
        for (int k = 0; k < BK; k++) {
            float4 a0 = *(const float4*)(&As[k][ty * 4]);
            float4 a1 = *(const float4*)(&As[k][64 + ty * 4]);
            float4 b0 = *(const float4*)(&Bs[k][tx * 4]);
            float4 b1 = *(const float4*)(&Bs[k][64 + tx * 4]);
            float ra[8] = {a0.x, a0.y, a0.z, a0.w, a1.x, a1.y, a1.z, a1.w};
            float rb[8] = {b0.x, b0.y, b0.z, b0.w, b1.x, b1.y, b1.z, b1.w};
#pragma unroll
            for (int i = 0; i < 8; i++)
#pragma unroll
                for (int j = 0; j < 8; j++) acc[i][j] += ra[i] * rb[j];
        }
        __syncthreads();
    }

    float4 bb0 = *(const float4*)(bias + bcol * BN + tx * 4);
    float4 bb1 = *(const float4*)(bias + bcol * BN + 64 + tx * 4);
    float bv[8] = {bb0.x, bb0.y, bb0.z, bb0.w, bb1.x, bb1.y, bb1.z, bb1.w};

#pragma unroll
    for (int i = 0; i < 8; i++) {
        int row = brow * BM + (i < 4 ? ty * 4 + i : 64 + ty * 4 + (i - 4));
        float* crow = C + (size_t)row * N + bcol * BN;
        float v[8];
#pragma unroll
        for (int j = 0; j < 8; j++) {
            float t = acc[i][j] + bv[j];
            if (RELU) t = fmaxf(t, 0.f);
            v[j] = t;
        }
        *(float4*)(crow + tx * 4)      = make_float4(v[0], v[1], v[2], v[3]);
        *(float4*)(crow + 64 + tx * 4) = make_float4(v[4], v[5], v[6], v[7]);
    }
}

// ================= all-fp16 tensor-core attention (ldmatrix) ==============
#define QH_STRIDE_W 36
#define VT_W 84
#define PS_W 84
#define SM_QH 0
#define SM_KH (NMAX * 144)
#define SM_VT (2 * NMAX * 144)
#define SM_PS (2 * NMAX * 144 + 64 * VT_W * 4)
#define ATTN_SMEM5 (SM_PS + 8 * 16 * PS_W * 4)

__global__ void __launch_bounds__(256, 2)
attention_tc_kernel(const __half* __restrict__ qkv, __half* __restrict__ out) {
    extern __shared__ char sm[];
    uint32_t sb = smem_u32(sm);
    uint32_t* Qh = (uint32_t*)(sm + SM_QH);
    uint32_t* Kh = (uint32_t*)(sm + SM_KH);
    __half*   Vt_h = (__half*)(sm + SM_VT);
    uint32_t* Ps = (uint32_t*)(sm + SM_PS);

    int g = blockIdx.x;
    int h = blockIdx.y;
    int s0 = g_start[g];
    int n  = g_start[g + 1] - s0;

    int tid  = threadIdx.x;
    int lane = tid & 31;
    int warp = tid >> 5;

    for (int idx = tid; idx < NMAX * 8; idx += 256) {
        int r = idx >> 3, q8 = idx & 7;
        uint4 hq = make_uint4(0, 0, 0, 0), hk = hq, hv = hq;
        if (r < n) {
            const __half* base = qkv + (size_t)(s0 + r) * (3 * DMODEL) + h * DHEAD + q8 * 8;
            hq = *(const uint4*)(base);
            hk = *(const uint4*)(base + DMODEL);
            hv = *(const uint4*)(base + 2 * DMODEL);
        }
        *(uint4*)((char*)Qh + r * 144 + q8 * 16) = hq;
        *(uint4*)((char*)Kh + r * 144 + q8 * 16) = hk;
        const __half* hv_h = (const __half*)&hv;
#pragma unroll
        for (int j = 0; j < 8; j++)
            Vt_h[(q8 * 8 + j) * (2 * VT_W) + r] = hv_h[j];
    }
    __syncthreads();

    int ntiles = (n + 15) >> 4;
    int nfc    = (n + 7) >> 3;
    int nfp    = 2 * ntiles;        // frags touched by PV
    int r = lane >> 2;
    int c = lane & 3;
    int lr  = lane & 7;
    int seg = lane >> 3;
    uint32_t* Pw = Ps + warp * 16 * PS_W;
    __half2*  Pw_h2 = (__half2*)Pw;
    uint32_t pw_base = sb + SM_PS + warp * 16 * PS_W * 4;

#pragma unroll 1
    for (int mt = warp; mt < ntiles; mt += 8) {
        int m0 = mt * 16;

        uint32_t q_addr = sb + SM_QH + (m0 + lr + (seg & 1) * 8) * 144 + (seg >> 1) * 16;
        uint32_t aq[4][4];
#pragma unroll
        for (int ks = 0; ks < 4; ks++)
            LDSM_X4(aq[ks][0], aq[ks][1], aq[ks][2], aq[ks][3], q_addr + ks * 32);

        uint32_t k_addr = sb + SM_KH + lr * 144 + (seg & 1) * 16;
        float s[20][4];
#pragma unroll
        for (int nf = 0; nf < 20; nf++) {
            s[nf][0] = 0.f; s[nf][1] = 0.f; s[nf][2] = 0.f; s[nf][3] = 0.f;
        }
#pragma unroll
        for (int nf = 0; nf < 20; nf++) {
            if (nf >= nfc) continue;
            uint32_t ka = k_addr + nf * (8 * 144);
#pragma unroll
            for (int ks = 0; ks < 4; ks++) {
                uint32_t bf[2];
                LDSM_X2(bf[0], bf[1], ka + ks * 32);
                mma_f16(s[nf], aq[ks], bf);
            }
        }

        // mask + scale + rowmax (bounded by nfc)
        float mx0 = -1e30f, mx1 = -1e30f;
#pragma unroll
        for (int nf = 0; nf < 20; nf++) {
            if (nf >= nfc) continue;
            int col0 = nf * 8 + 2 * c;
            s[nf][0] = (col0     < n) ? s[nf][0] * 0.125f : -1e30f;
            s[nf][1] = (col0 + 1 < n) ? s[nf][1] * 0.125f : -1e30f;
            s[nf][2] = (col0     < n) ? s[nf][2] * 0.125f : -1e30f;
            s[nf][3] = (col0 + 1 < n) ? s[nf][3] * 0.125f : -1e30f;
            mx0 = fmaxf(mx0, fmaxf(s[nf][0], s[nf][1]));
            mx1 = fmaxf(mx1, fmaxf(s[nf][2], s[nf][3]));
        }
        mx0 = fmaxf(mx0, __shfl_xor_sync(0xffffffffu, mx0, 1));
        mx0 = fmaxf(mx0, __shfl_xor_sync(0xffffffffu, mx0, 2));
        mx1 = fmaxf(mx1, __shfl_xor_sync(0xffffffffu, mx1, 1));
        mx1 = fmaxf(mx1, __shfl_xor_sync(0xffffffffu, mx1, 2));

        // exp + sum (bounded by nfc)
        float sum0 = 0.f, sum1 = 0.f;
#pragma unroll
        for (int nf = 0; nf < 20; nf++) {
            if (nf >= nfc) continue;
            float p0 = __expf(s[nf][0] - mx0);
            float p1 = __expf(s[nf][1] - mx0);
            float p2 = __expf(s[nf][2] - mx1);
            float p3 = __expf(s[nf][3] - mx1);
            s[nf][0] = p0; s[nf][1] = p1; s[nf][2] = p2; s[nf][3] = p3;
            sum0 += p0 + p1;
            sum1 += p2 + p3;
        }
        sum0 += __shfl_xor_sync(0xffffffffu, sum0, 1);
        sum0 += __shfl_xor_sync(0xffffffffu, sum0, 2);
        sum1 += __shfl_xor_sync(0xffffffffu, sum1, 1);
        sum1 += __shfl_xor_sync(0xffffffffu, sum1, 2);
        float inv0 = 1.f / sum0;
        float inv1 = 1.f / sum1;

        // P -> smem: computed frags [0,nfc), zero frags [nfc, nfp)
        __syncwarp();
#pragma unroll
        for (int nf = 0; nf < 20; nf++) {
            if (nf >= nfp) continue;
            int colw = nf * 4 + c;
            if (nf < nfc) {
                Pw_h2[r * PS_W + colw]       = __floats2half2_rn(s[nf][0], s[nf][1]);
                Pw_h2[(r + 8) * PS_W + colw] = __floats2half2_rn(s[nf][2], s[nf][3]);
            } else {
                Pw_h2[r * PS_W + colw]       = __floats2half2_rn(0.f, 0.f);
                Pw_h2[(r + 8) * PS_W + colw] = __floats2half2_rn(0.f, 0.f);
            }
        }
        __syncwarp();

        // O = P V
        uint32_t p_addr = pw_base + (lr + (seg & 1) * 8) * (PS_W * 4) + (seg >> 1) * 16;
        uint32_t v_addr = sb + SM_VT + lr * (VT_W * 4) + (seg & 1) * 16;
        float o[8][4];
#pragma unroll
        for (int nd = 0; nd < 8; nd++) {
            o[nd][0] = 0.f; o[nd][1] = 0.f; o[nd][2] = 0.f; o[nd][3] = 0.f;
        }
#pragma unroll
        for (int ks = 0; ks < 10; ks++) {
            if (ks >= ntiles) continue;
            uint32_t ap[4];
            LDSM_X4(ap[0], ap[1], ap[2], ap[3], p_addr + ks * 32);
#pragma unroll
            for (int nd = 0; nd < 8; nd++) {
                uint32_t bf[2];
                LDSM_X2(bf[0], bf[1], v_addr + nd * (8 * VT_W * 4) + ks * 32);
                mma_f16(o[nd], ap, bf);
            }
        }

        int row0 = m0 + r, row1 = m0 + r + 8;
#pragma unroll
        for (int nd = 0; nd < 8; nd++) {
            int col = h * DHEAD + nd * 8 + 2 * c;
            if (row0 < n)
                *(__half2*)(out + (size_t)(s0 + row0) * DMODEL + col) =
                    __floats2half2_rn(o[nd][0] * inv0, o[nd][1] * inv0);
            if (row1 < n)
                *(__half2*)(out + (size_t)(s0 + row1) * DMODEL + col) =
                    __floats2half2_rn(o[nd][2] * inv1, o[nd][3] * inv1);
        }
        __syncwarp();
    }
}

// ---------------- masked mean pool (fp16 in, fp32 out) ----------------
__global__ void pool_kernel(const __half* __restrict__ hin, float* __restrict__ pooled) {
    int g = blockIdx.x;
    int d = threadIdx.x;
    int s0 = g_start[g];
    int n  = g_start[g + 1] - s0;
    float s = 0.f;
    for (int r = 0; r < n; r++) s += __half2float(hin[(size_t)(s0 + r) * DMODEL + d]);
    pooled[g * DMODEL + d] = s / (float)n;
}

// ---------------- final 128 -> 1 dot ----------------
__global__ void final_kernel(const float* __restrict__ h2, const float* __restrict__ w,
                             const float* __restrict__ b, float* __restrict__ out) {
    __shared__ float red[128];
    int g = blockIdx.x;
    int t = threadIdx.x;
    red[t] = h2[g * 128 + t] * w[t];
    __syncthreads();
    for (int s = 64; s; s >>= 1) {
        if (t < s) red[t] += red[t + s];
        __syncthreads();
    }
    if (t == 0) out[g] = red[0] + b[0];
}

// ---------------- launch ----------------
extern "C" void kernel_launch(void* const* d_in, const int* in_sizes, int n_in,
                              void* d_out, int out_size) {
    const float* x      = (const float*)d_in[0];
    const int*   batch  = (const int*)  d_in[1];
    const float* in_w1  = (const float*)d_in[2];
    const float* in_b1  = (const float*)d_in[3];
    const float* out_w1 = (const float*)d_in[4];
    const float* out_b1 = (const float*)d_in[5];
    const float* in_w2  = (const float*)d_in[6];
    const float* in_b2  = (const float*)d_in[7];
    const float* out_w2 = (const float*)d_in[8];
    const float* out_b2 = (const float*)d_in[9];
    const float* r_w1   = (const float*)d_in[10];
    const float* r_b1   = (const float*)d_in[11];
    const float* r_w2   = (const float*)d_in[12];
    const float* r_b2   = (const float*)d_in[13];
    const float* r_w3   = (const float*)d_in[14];
    const float* r_b3   = (const float*)d_in[15];
    float* out = (float*)d_out;

    __half *qkv, *bufA, *bufB, *xh, *w1h, *w2h, *ow2h, *wo1t, *wcomb;
    float *pooled, *r1, *r2, *bcomb, *zero256;
    cudaGetSymbolAddress((void**)&qkv,    g_qkv);
    cudaGetSymbolAddress((void**)&bufA,   g_bufA);
    cudaGetSymbolAddress((void**)&bufB,   g_bufB);
    cudaGetSymbolAddress((void**)&xh,     g_xh);
    cudaGetSymbolAddress((void**)&w1h,    g_w1h);
    cudaGetSymbolAddress((void**)&w2h,    g_w2h);
    cudaGetSymbolAddress((void**)&ow2h,   g_ow2h);
    cudaGetSymbolAddress((void**)&wo1t,   g_wo1t);
    cudaGetSymbolAddress((void**)&wcomb,  g_wcomb);
    cudaGetSymbolAddress((void**)&bcomb,  g_bcomb);
    cudaGetSymbolAddress((void**)&zero256, g_zero256);
    cudaGetSymbolAddress((void**)&pooled, g_pooled);
    cudaGetSymbolAddress((void**)&r1,     g_r1);
    cudaGetSymbolAddress((void**)&r2,     g_r2);

    cudaFuncSetAttribute(attention_tc_kernel,
                         cudaFuncAttributeMaxDynamicSharedMemorySize, ATTN_SMEM5);
    cudaFuncSetAttribute(h16_gemm_kernel,
                         cudaFuncAttributeMaxDynamicSharedMemorySize, TCG_SMEM);

    compute_starts_kernel<<<(TOTAL_ATOMS + 255) / 256, 256>>>(batch);

    int totF4 = NX4 + 2 * NW4 + NO4;
    f2h_all_kernel<<<(totF4 + 255) / 256, 256>>>(x, in_w1, in_w2, out_w2,
                                                 xh, w1h, w2h, ow2h);

    // ---- precompute fused layer weights: Wcomb = Wi2 @ Wo1, bcomb ----
    dim3 tgrid(8, 8), tblk(32, 32);
    transpose_h_kernel<<<tgrid, tblk>>>(out_w1, wo1t);
    dim3 gPC(2, 6);   // N=256, M=768
    h16_gemm_kernel<<<gPC, 256, TCG_SMEM>>>(w2h, wo1t, zero256, wcomb, DMODEL);
    bcomb_kernel<<<3, 256>>>(in_w2, out_b1, in_b2, bcomb);

    dim3 gQKV(3 * DMODEL / 128, TOTAL_ATOMS / 128);
    dim3 gOUT(DMODEL / 128, TOTAL_ATOMS / 128);
    dim3 gATT(NUM_GRAPHS, NHEAD);

    // layer 1: in_proj + attention
    h16_gemm_kernel<<<gQKV, 256, TCG_SMEM>>>(xh, w1h, in_b1, qkv, 3 * DMODEL);
    attention_tc_kernel<<<gATT, 256, ATTN_SMEM5>>>(qkv, bufA);

    // fused out_proj(L1) + in_proj(L2)
    h16_gemm_kernel<<<gQKV, 256, TCG_SMEM>>>(bufA, wcomb, bcomb, qkv, 3 * DMODEL);
    attention_tc_kernel<<<gATT, 256, ATTN_SMEM5>>>(qkv, bufA);

    // layer 2 out_proj
    h16_gemm_kernel<<<gOUT, 256, TCG_SMEM>>>(bufA, ow2h, out_b2, bufB, DMODEL);

    // pool + readout MLP
    pool_kernel<<<NUM_GRAPHS, DMODEL>>>(bufB, pooled);

    dim3 gR1(DMODEL / 128, NUM_GRAPHS / 128);
    gemm_tn_kernel<true><<<gR1, 256>>>(pooled, r_w1, r_b1, r1, NUM_GRAPHS, DMODEL, DMODEL);
    dim3 gR2(1, NUM_GRAPHS / 128);
    gemm_tn_kernel<true><<<gR2, 256>>>(r1, r_w2, r_b2, r2, NUM_GRAPHS, 128, DMODEL);
    final_kernel<<<NUM_GRAPHS, 128>>>(r2, r_w3, r_b3, out);
}

// round 15
// speedup vs baseline: 1.0453x; 1.0453x over previous
#include <cuda_runtime.h>
#include <cuda_fp16.h>
#include <cstdint>
#include <math.h>

#define TOTAL_ATOMS 65536
#define NUM_GRAPHS  512
#define DMODEL      256
#define NHEAD       4
#define DHEAD       64
#define NMAX        160

// ---------------- scratch ----------------
__device__ __half g_qkv [ (size_t)TOTAL_ATOMS * 3 * DMODEL ];
__device__ __half g_bufA[ (size_t)TOTAL_ATOMS * DMODEL ];
__device__ __half g_xh  [ (size_t)TOTAL_ATOMS * DMODEL ];
__device__ __half g_w1h [ 3 * DMODEL * DMODEL ];
__device__ __half g_w2h [ 3 * DMODEL * DMODEL ];
__device__ __half g_wo1t[ DMODEL * DMODEL ];          // Wo1^T fp16
__device__ __half g_wcomb[ 3 * DMODEL * DMODEL ];     // Wi2 @ Wo1 fp16
__device__ float  g_bcomb[ 3 * DMODEL ];              // Wi2 @ bo1 + bi2
__device__ float  g_zero256[ DMODEL ];                // zero-initialized
__device__ float g_pooled [ NUM_GRAPHS * DMODEL ];
__device__ float g_pooled2[ NUM_GRAPHS * DMODEL ];
__device__ float g_r1    [ NUM_GRAPHS * DMODEL ];
__device__ float g_r2    [ NUM_GRAPHS * 128 ];
__device__ int   g_start [ NUM_GRAPHS + 1 ];

// ---------------- per-graph start offsets ----------------
__global__ void compute_starts_kernel(const int* __restrict__ batch) {
    int i = blockIdx.x * blockDim.x + threadIdx.x;
    if (i >= TOTAL_ATOMS) return;
    if (i == 0) {
        g_start[batch[0]] = 0;
        g_start[NUM_GRAPHS] = TOTAL_ATOMS;
    } else if (batch[i] != batch[i - 1]) {
        g_start[batch[i]] = i;
    }
}

// ---------------- fused fp32 -> fp16 convert (x + 2 weight blocks) --------
#define NX4 (TOTAL_ATOMS * DMODEL / 4)
#define NW4 (3 * DMODEL * DMODEL / 4)
__global__ void f2h_all_kernel(const float* __restrict__ x,
                               const float* __restrict__ w1,
                               const float* __restrict__ w2,
                               __half* __restrict__ xh,
                               __half* __restrict__ w1h,
                               __half* __restrict__ w2h) {
    int i = blockIdx.x * blockDim.x + threadIdx.x;
    const float* src;
    __half* dst;
    int off;
    if (i < NX4)                { src = x;  dst = xh;  off = i; }
    else if (i < NX4 + NW4)     { src = w1; dst = w1h; off = i - NX4; }
    else if (i < NX4 + 2 * NW4) { src = w2; dst = w2h; off = i - NX4 - NW4; }
    else return;
    float4 v = ((const float4*)src)[off];
    __half2* d = (__half2*)dst + off * 2;
    d[0] = __floats2half2_rn(v.x, v.y);
    d[1] = __floats2half2_rn(v.z, v.w);
}

// ---------------- transpose-convert: dst[j][k] = half(src[k][j]), 256x256 --
__global__ void transpose_h_kernel(const float* __restrict__ src, __half* __restrict__ dst) {
    __shared__ float tile[32][33];
    int bx = blockIdx.x * 32, by = blockIdx.y * 32;
    tile[threadIdx.y][threadIdx.x] = src[(by + threadIdx.y) * DMODEL + bx + threadIdx.x];
    __syncthreads();
    dst[(bx + threadIdx.y) * DMODEL + by + threadIdx.x] =
        __float2half(tile[threadIdx.x][threadIdx.y]);
}

// ---------------- bcomb[i] = dot(Wi2[i,:], bo1) + bi2[i], block-per-row ----
__global__ void bcomb_kernel(const float* __restrict__ w2, const float* __restrict__ bo1,
                             const float* __restrict__ bi2, float* __restrict__ bcomb) {
    int i = blockIdx.x;      // 768 rows
    int t = threadIdx.x;     // 128 threads
    float s = w2[i * DMODEL + t] * bo1[t] + w2[i * DMODEL + t + 128] * bo1[t + 128];
#pragma unroll
    for (int o = 16; o; o >>= 1) s += __shfl_xor_sync(0xffffffffu, s, o);
    __shared__ float red[4];
    if ((t & 31) == 0) red[t >> 5] = s;
    __syncthreads();
    if (t == 0) bcomb[i] = red[0] + red[1] + red[2] + red[3] + bi2[i];
}

// ---------------- asm helpers ----------------
__device__ __forceinline__ uint32_t smem_u32(const void* p) {
    uint32_t a;
    asm("{ .reg .u64 t; cvta.to.shared.u64 t, %1; cvt.u32.u64 %0, t; }" : "=r"(a) : "l"(p));
    return a;
}
__device__ __forceinline__ void mma_f16(float* d, const uint32_t* a, const uint32_t* b) {
    asm volatile(
        "mma.sync.aligned.m16n8k16.row.col.f32.f16.f16.f32 "
        "{%0,%1,%2,%3}, {%4,%5,%6,%7}, {%8,%9}, {%0,%1,%2,%3};"
        : "+f"(d[0]), "+f"(d[1]), "+f"(d[2]), "+f"(d[3])
        : "r"(a[0]), "r"(a[1]), "r"(a[2]), "r"(a[3]), "r"(b[0]), "r"(b[1]));
}
#define LDSM_X4(r0, r1, r2, r3, addr) \
    asm volatile("ldmatrix.sync.aligned.m8n8.x4.shared.b16 {%0,%1,%2,%3}, [%4];" \
        : "=r"(r0), "=r"(r1), "=r"(r2), "=r"(r3) : "r"(addr))
#define LDSM_X2(r0, r1, addr) \
    asm volatile("ldmatrix.sync.aligned.m8n8.x2.shared.b16 {%0,%1}, [%2];" \
        : "=r"(r0), "=r"(r1) : "r"(addr))
#define CP_ASYNC16(dst, src) \
    asm volatile("cp.async.cg.shared.global [%0], [%1], 16;" :: "r"(dst), "l"(src))
#define CP_COMMIT() asm volatile("cp.async.commit_group;" ::: "memory")
#define CP_WAIT2()  asm volatile("cp.async.wait_group 2;" ::: "memory")

// ================= fp16 GEMM, 128x128 tile (R10 proven config) ============
#define STAGE_BYTES 20480
#define TCG_SMEM (4 * STAGE_BYTES)

__global__ void __launch_bounds__(256, 2)
h16_gemm_kernel(const __half* __restrict__ A, const __half* __restrict__ B,
                const float* __restrict__ bias, __half* __restrict__ C, int Ntot) {
    extern __shared__ char smem[];
    uint32_t sbase = smem_u32(smem);
    const int K = DMODEL;

    int tid   = threadIdx.x;
    int lane  = tid & 31;
    int wid   = tid >> 5;
    int warpM = wid & 1;
    int warpN = wid >> 1;
    int m0 = blockIdx.y * 128;
    int n0 = blockIdx.x * 128;

    const __half* Ab = A + (size_t)m0 * K;
    const __half* Bb = B + (size_t)n0 * K;

    int ar0 = tid >> 2;
    int aq  = tid & 3;
    int ar1 = ar0 + 64;
    uint32_t adst0 = ar0 * 80 + aq * 16;
    uint32_t adst1 = ar1 * 80 + aq * 16;
    const __half* asrc0 = Ab + (size_t)ar0 * K + aq * 8;
    const __half* asrc1 = Ab + (size_t)ar1 * K + aq * 8;
    const __half* bsrc0 = Bb + (size_t)ar0 * K + aq * 8;
    const __half* bsrc1 = Bb + (size_t)ar1 * K + aq * 8;

    int lr  = lane & 7;
    int seg = lane >> 3;
    uint32_t aoff = (uint32_t)((warpM * 64 + lr + (seg & 1) * 8) * 80 + (seg >> 1) * 16);
    uint32_t boff = (uint32_t)(10240 + (warpN * 32 + lr) * 80 + (seg & 1) * 16);

    float acc[4][4][4];
#pragma unroll
    for (int mt = 0; mt < 4; mt++)
#pragma unroll
        for (int nt = 0; nt < 4; nt++)
#pragma unroll
            for (int j = 0; j < 4; j++) acc[mt][nt][j] = 0.f;

#pragma unroll
    for (int s = 0; s < 3; s++) {
        uint32_t stg = sbase + s * STAGE_BYTES;
        int k0 = s * 32;
        CP_ASYNC16(stg + adst0,         asrc0 + k0);
        CP_ASYNC16(stg + adst1,         asrc1 + k0);
        CP_ASYNC16(stg + 10240 + adst0, bsrc0 + k0);
        CP_ASYNC16(stg + 10240 + adst1, bsrc1 + k0);
        CP_COMMIT();
    }

#pragma unroll 1
    for (int ch = 0; ch < 8; ch++) {
        CP_WAIT2();
        __syncthreads();

        if (ch + 3 < 8) {
            uint32_t stg = sbase + ((ch + 3) & 3) * STAGE_BYTES;
            int k0 = (ch + 3) * 32;
            CP_ASYNC16(stg + adst0,         asrc0 + k0);
            CP_ASYNC16(stg + adst1,         asrc1 + k0);
            CP_ASYNC16(stg + 10240 + adst0, bsrc0 + k0);
            CP_ASYNC16(stg + 10240 + adst1, bsrc1 + k0);
        }
        CP_COMMIT();

        uint32_t st = sbase + (ch & 3) * STAGE_BYTES;

#pragma unroll
        for (int ks = 0; ks < 2; ks++) {
            uint32_t af[4][4];
#pragma unroll
            for (int mt = 0; mt < 4; mt++)
                LDSM_X4(af[mt][0], af[mt][1], af[mt][2], af[mt][3],
                        st + aoff + mt * 1280 + ks * 32);
            uint32_t bf[4][2];
#pragma unroll
            for (int nt = 0; nt < 4; nt++)
                LDSM_X2(bf[nt][0], bf[nt][1],
                        st + boff + nt * 640 + ks * 32);
#pragma unroll
            for (int mt = 0; mt < 4; mt++)
#pragma unroll
                for (int nt = 0; nt < 4; nt++)
                    mma_f16(acc[mt][nt], af[mt], bf[nt]);
        }
    }

    int r  = lane >> 2;
    int c2 = (lane & 3) * 2;
#pragma unroll
    for (int nt = 0; nt < 4; nt++) {
        int col = n0 + warpN * 32 + nt * 8 + c2;
        float bx = bias[col], by = bias[col + 1];
#pragma unroll
        for (int mt = 0; mt < 4; mt++) {
            int row = m0 + warpM * 64 + mt * 16 + r;
            __half2* p0 = (__half2*)(C + (size_t)row * Ntot + col);
            __half2* p1 = (__half2*)(C + (size_t)(row + 8) * Ntot + col);
            *p0 = __floats2half2_rn(acc[mt][nt][0] + bx, acc[mt][nt][1] + by);
            *p1 = __floats2half2_rn(acc[mt][nt][2] + bx, acc[mt][nt][3] + by);
        }
    }
}

// ---------------- fp32 GEMM (small readout layers) ----------------
template <bool RELU>
__global__ void __launch_bounds__(256)
gemm_tn_kernel(const float* __restrict__ A, const float* __restrict__ B,
               const float* __restrict__ bias, float* __restrict__ C,
               int M, int N, int K) {
    const int BM = 128, BN = 128, BK = 8;
    __shared__ float As[BK][BM];
    __shared__ float Bs[BK][BN];

    int tid  = threadIdx.x;
    int brow = blockIdx.y;
    int bcol = blockIdx.x;

    const float* Ab = A + (size_t)brow * BM * K;
    const float* Bb = B + (size_t)bcol * BN * K;

    int lr = tid >> 1;
    int lc = (tid & 1) * 4;
    int ty = tid >> 4;
    int tx = tid & 15;

    float acc[8][8];
#pragma unroll
    for (int i = 0; i < 8; i++)
#pragma unroll
        for (int j = 0; j < 8; j++) acc[i][j] = 0.f;

    for (int k0 = 0; k0 < K; k0 += BK) {
        float4 a = *(const float4*)(Ab + (size_t)lr * K + k0 + lc);
        float4 b = *(const float4*)(Bb + (size_t)lr * K + k0 + lc);
        As[lc + 0][lr] = a.x; As[lc + 1][lr] = a.y;
        As[lc + 2][lr] = a.z; As[lc + 3][lr] = a.w;
        Bs[lc + 0][lr] = b.x; Bs[lc + 1][lr] = b.y;
        Bs[lc + 2][lr] = b.z; Bs[lc + 3][lr] = b.w;
        __syncthreads();
#pragma unroll
        for (int k = 0; k < BK; k++) {
            float4 a0 = *(const float4*)(&As[k][ty * 4]);
            float4 a1 = *(const float4*)(&As[k][64 + ty * 4]);
            float4 b0 = *(const float4*)(&Bs[k][tx * 4]);
            float4 b1 = *(const float4*)(&Bs[k][64 + tx * 4]);
            float ra[8] = {a0.x, a0.y, a0.z, a0.w, a1.x, a1.y, a1.z, a1.w};
            float rb[8] = {b0.x, b0.y, b0.z, b0.w, b1.x, b1.y, b1.z, b1.w};
#pragma unroll
            for (int i = 0; i < 8; i++)
#pragma unroll
                for (int j = 0; j < 8; j++) acc[i][j] += ra[i] * rb[j];
        }
        __syncthreads();
    }

    float4 bb0 = *(const float4*)(bias + bcol * BN + tx * 4);
    float4 bb1 = *(const float4*)(bias + bcol * BN + 64 + tx * 4);
    float bv[8] = {bb0.x, bb0.y, bb0.z, bb0.w, bb1.x, bb1.y, bb1.z, bb1.w};

#pragma unroll
    for (int i = 0; i < 8; i++) {
        int row = brow * BM + (i < 4 ? ty * 4 + i : 64 + ty * 4 + (i - 4));
        float* crow = C + (size_t)row * N + bcol * BN;
        float v[8];
#pragma unroll
        for (int j = 0; j < 8; j++) {
            float t = acc[i][j] + bv[j];
            if (RELU) t = fmaxf(t, 0.f);
            v[j] = t;
        }
        *(float4*)(crow + tx * 4)      = make_float4(v[0], v[1], v[2], v[3]);
        *(float4*)(crow + 64 + tx * 4) = make_float4(v[4], v[5], v[6], v[7]);
    }
}

// ================= all-fp16 tensor-core attention (ldmatrix) ==============
#define QH_STRIDE_W 36
#define VT_W 84
#define PS_W 84
#define SM_QH 0
#define SM_KH (NMAX * 144)
#define SM_VT (2 * NMAX * 144)
#define SM_PS (2 * NMAX * 144 + 64 * VT_W * 4)
#define ATTN_SMEM5 (SM_PS + 8 * 16 * PS_W * 4)

__global__ void __launch_bounds__(256, 2)
attention_tc_kernel(const __half* __restrict__ qkv, __half* __restrict__ out) {
    extern __shared__ char sm[];
    uint32_t sb = smem_u32(sm);
    uint32_t* Qh = (uint32_t*)(sm + SM_QH);
    uint32_t* Kh = (uint32_t*)(sm + SM_KH);
    __half*   Vt_h = (__half*)(sm + SM_VT);
    uint32_t* Ps = (uint32_t*)(sm + SM_PS);

    int g = blockIdx.x;
    int h = blockIdx.y;
    int s0 = g_start[g];
    int n  = g_start[g + 1] - s0;

    int tid  = threadIdx.x;
    int lane = tid & 31;
    int warp = tid >> 5;

    for (int idx = tid; idx < NMAX * 8; idx += 256) {
        int r = idx >> 3, q8 = idx & 7;
        uint4 hq = make_uint4(0, 0, 0, 0), hk = hq, hv = hq;
        if (r < n) {
            const __half* base = qkv + (size_t)(s0 + r) * (3 * DMODEL) + h * DHEAD + q8 * 8;
            hq = *(const uint4*)(base);
            hk = *(const uint4*)(base + DMODEL);
            hv = *(const uint4*)(base + 2 * DMODEL);
        }
        *(uint4*)((char*)Qh + r * 144 + q8 * 16) = hq;
        *(uint4*)((char*)Kh + r * 144 + q8 * 16) = hk;
        const __half* hv_h = (const __half*)&hv;
#pragma unroll
        for (int j = 0; j < 8; j++)
            Vt_h[(q8 * 8 + j) * (2 * VT_W) + r] = hv_h[j];
    }
    __syncthreads();

    int ntiles = (n + 15) >> 4;
    int nfc    = (n + 7) >> 3;
    int nfp    = 2 * ntiles;
    int r = lane >> 2;
    int c = lane & 3;
    int lr  = lane & 7;
    int seg = lane >> 3;
    uint32_t* Pw = Ps + warp * 16 * PS_W;
    __half2*  Pw_h2 = (__half2*)Pw;                 // 4-byte units: offset = warp*16*PS_W
    uint32_t pw_base = sb + SM_PS + warp * 16 * PS_W * 4;

#pragma unroll 1
    for (int mt = warp; mt < ntiles; mt += 8) {
        int m0 = mt * 16;

        uint32_t q_addr = sb + SM_QH + (m0 + lr + (seg & 1) * 8) * 144 + (seg >> 1) * 16;
        uint32_t aq[4][4];
#pragma unroll
        for (int ks = 0; ks < 4; ks++)
            LDSM_X4(aq[ks][0], aq[ks][1], aq[ks][2], aq[ks][3], q_addr + ks * 32);

        uint32_t k_addr = sb + SM_KH + lr * 144 + (seg & 1) * 16;
        float s[20][4];
#pragma unroll
        for (int nf = 0; nf < 20; nf++) {
            s[nf][0] = 0.f; s[nf][1] = 0.f; s[nf][2] = 0.f; s[nf][3] = 0.f;
        }
#pragma unroll
        for (int nf = 0; nf < 20; nf++) {
            if (nf >= nfc) continue;
            uint32_t ka = k_addr + nf * (8 * 144);
#pragma unroll
            for (int ks = 0; ks < 4; ks++) {
                uint32_t bf[2];
                LDSM_X2(bf[0], bf[1], ka + ks * 32);
                mma_f16(s[nf], aq[ks], bf);
            }
        }

        float mx0 = -1e30f, mx1 = -1e30f;
#pragma unroll
        for (int nf = 0; nf < 20; nf++) {
            if (nf >= nfc) continue;
            int col0 = nf * 8 + 2 * c;
            s[nf][0] = (col0     < n) ? s[nf][0] * 0.125f : -1e30f;
            s[nf][1] = (col0 + 1 < n) ? s[nf][1] * 0.125f : -1e30f;
            s[nf][2] = (col0     < n) ? s[nf][2] * 0.125f : -1e30f;
            s[nf][3] = (col0 + 1 < n) ? s[nf][3] * 0.125f : -1e30f;
            mx0 = fmaxf(mx0, fmaxf(s[nf][0], s[nf][1]));
            mx1 = fmaxf(mx1, fmaxf(s[nf][2], s[nf][3]));
        }
        mx0 = fmaxf(mx0, __shfl_xor_sync(0xffffffffu, mx0, 1));
        mx0 = fmaxf(mx0, __shfl_xor_sync(0xffffffffu, mx0, 2));
        mx1 = fmaxf(mx1, __shfl_xor_sync(0xffffffffu, mx1, 1));
        mx1 = fmaxf(mx1, __shfl_xor_sync(0xffffffffu, mx1, 2));

        float sum0 = 0.f, sum1 = 0.f;
#pragma unroll
        for (int nf = 0; nf < 20; nf++) {
            if (nf >= nfc) continue;
            float p0 = __expf(s[nf][0] - mx0);
            float p1 = __expf(s[nf][1] - mx0);
            float p2 = __expf(s[nf][2] - mx1);
            float p3 = __expf(s[nf][3] - mx1);
            s[nf][0] = p0; s[nf][1] = p1; s[nf][2] = p2; s[nf][3] = p3;
            sum0 += p0 + p1;
            sum1 += p2 + p3;
        }
        sum0 += __shfl_xor_sync(0xffffffffu, sum0, 1);
        sum0 += __shfl_xor_sync(0xffffffffu, sum0, 2);
        sum1 += __shfl_xor_sync(0xffffffffu, sum1, 1);
        sum1 += __shfl_xor_sync(0xffffffffu, sum1, 2);
        float inv0 = 1.f / sum0;
        float inv1 = 1.f / sum1;

        __syncwarp();
#pragma unroll
        for (int nf = 0; nf < 20; nf++) {
            if (nf >= nfp) continue;
            int colw = nf * 4 + c;
            if (nf < nfc) {
                Pw_h2[r * PS_W + colw]       = __floats2half2_rn(s[nf][0], s[nf][1]);
                Pw_h2[(r + 8) * PS_W + colw] = __floats2half2_rn(s[nf][2], s[nf][3]);
            } else {
                Pw_h2[r * PS_W + colw]       = __floats2half2_rn(0.f, 0.f);
                Pw_h2[(r + 8) * PS_W + colw] = __floats2half2_rn(0.f, 0.f);
            }
        }
        __syncwarp();

        uint32_t p_addr = pw_base + (lr + (seg & 1) * 8) * (PS_W * 4) + (seg >> 1) * 16;
        uint32_t v_addr = sb + SM_VT + lr * (VT_W * 4) + (seg & 1) * 16;
        float o[8][4];
#pragma unroll
        for (int nd = 0; nd < 8; nd++) {
            o[nd][0] = 0.f; o[nd][1] = 0.f; o[nd][2] = 0.f; o[nd][3] = 0.f;
        }
#pragma unroll
        for (int ks = 0; ks < 10; ks++) {
            if (ks >= ntiles) continue;
            uint32_t ap[4];
            LDSM_X4(ap[0], ap[1], ap[2], ap[3], p_addr + ks * 32);
#pragma unroll
            for (int nd = 0; nd < 8; nd++) {
                uint32_t bf[2];
                LDSM_X2(bf[0], bf[1], v_addr + nd * (8 * VT_W * 4) + ks * 32);
                mma_f16(o[nd], ap, bf);
            }
        }

        int row0 = m0 + r, row1 = m0 + r + 8;
#pragma unroll
        for (int nd = 0; nd < 8; nd++) {
            int col = h * DHEAD + nd * 8 + 2 * c;
            if (row0 < n)
                *(__half2*)(out + (size_t)(s0 + row0) * DMODEL + col) =
                    __floats2half2_rn(o[nd][0] * inv0, o[nd][1] * inv0);
            if (row1 < n)
                *(__half2*)(out + (size_t)(s0 + row1) * DMODEL + col) =
                    __floats2half2_rn(o[nd][2] * inv1, o[nd][3] * inv1);
        }
        __syncwarp();
    }
}

// ---------------- masked mean pool (fp16 in, fp32 out) ----------------
__global__ void pool_kernel(const __half* __restrict__ hin, float* __restrict__ pooled) {
    int g = blockIdx.x;
    int d = threadIdx.x;
    int s0 = g_start[g];
    int n  = g_start[g + 1] - s0;
    float s = 0.f;
    for (int r = 0; r < n; r++) s += __half2float(hin[(size_t)(s0 + r) * DMODEL + d]);
    pooled[g * DMODEL + d] = s / (float)n;
}

// ---------------- final 128 -> 1 dot ----------------
__global__ void final_kernel(const float* __restrict__ h2, const float* __restrict__ w,
                             const float* __restrict__ b, float* __restrict__ out) {
    __shared__ float red[128];
    int g = blockIdx.x;
    int t = threadIdx.x;
    red[t] = h2[g * 128 + t] * w[t];
    __syncthreads();
    for (int s = 64; s; s >>= 1) {
        if (t < s) red[t] += red[t + s];
        __syncthreads();
    }
    if (t == 0) out[g] = red[0] + b[0];
}

// ---------------- launch ----------------
extern "C" void kernel_launch(void* const* d_in, const int* in_sizes, int n_in,
                              void* d_out, int out_size) {
    const float* x      = (const float*)d_in[0];
    const int*   batch  = (const int*)  d_in[1];
    const float* in_w1  = (const float*)d_in[2];
    const float* in_b1  = (const float*)d_in[3];
    const float* out_w1 = (const float*)d_in[4];
    const float* out_b1 = (const float*)d_in[5];
    const float* in_w2  = (const float*)d_in[6];
    const float* in_b2  = (const float*)d_in[7];
    const float* out_w2 = (const float*)d_in[8];
    const float* out_b2 = (const float*)d_in[9];
    const float* r_w1   = (const float*)d_in[10];
    const float* r_b1   = (const float*)d_in[11];
    const float* r_w2   = (const float*)d_in[12];
    const float* r_b2   = (const float*)d_in[13];
    const float* r_w3   = (const float*)d_in[14];
    const float* r_b3   = (const float*)d_in[15];
    float* out = (float*)d_out;

    __half *qkv, *bufA, *xh, *w1h, *w2h, *wo1t, *wcomb;
    float *pooled, *pooled2, *r1, *r2, *bcomb, *zero256;
    cudaGetSymbolAddress((void**)&qkv,    g_qkv);
    cudaGetSymbolAddress((void**)&bufA,   g_bufA);
    cudaGetSymbolAddress((void**)&xh,     g_xh);
    cudaGetSymbolAddress((void**)&w1h,    g_w1h);
    cudaGetSymbolAddress((void**)&w2h,    g_w2h);
    cudaGetSymbolAddress((void**)&wo1t,   g_wo1t);
    cudaGetSymbolAddress((void**)&wcomb,  g_wcomb);
    cudaGetSymbolAddress((void**)&bcomb,  g_bcomb);
    cudaGetSymbolAddress((void**)&zero256, g_zero256);
    cudaGetSymbolAddress((void**)&pooled, g_pooled);
    cudaGetSymbolAddress((void**)&pooled2, g_pooled2);
    cudaGetSymbolAddress((void**)&r1,     g_r1);
    cudaGetSymbolAddress((void**)&r2,     g_r2);

    cudaFuncSetAttribute(attention_tc_kernel,
                         cudaFuncAttributeMaxDynamicSharedMemorySize, ATTN_SMEM5);
    cudaFuncSetAttribute(h16_gemm_kernel,
                         cudaFuncAttributeMaxDynamicSharedMemorySize, TCG_SMEM);

    compute_starts_kernel<<<(TOTAL_ATOMS + 255) / 256, 256>>>(batch);

    int totF4 = NX4 + 2 * NW4;
    f2h_all_kernel<<<(totF4 + 255) / 256, 256>>>(x, in_w1, in_w2, xh, w1h, w2h);

    // ---- precompute fused layer weights: Wcomb = Wi2 @ Wo1, bcomb ----
    dim3 tgrid(8, 8), tblk(32, 32);
    transpose_h_kernel<<<tgrid, tblk>>>(out_w1, wo1t);
    dim3 gPC(2, 6);
    h16_gemm_kernel<<<gPC, 256, TCG_SMEM>>>(w2h, wo1t, zero256, wcomb, DMODEL);
    bcomb_kernel<<<3 * DMODEL, 128>>>(in_w2, out_b1, in_b2, bcomb);

    dim3 gQKV(3 * DMODEL / 128, TOTAL_ATOMS / 128);
    dim3 gATT(NUM_GRAPHS, NHEAD);

    // layer 1: in_proj + attention
    h16_gemm_kernel<<<gQKV, 256, TCG_SMEM>>>(xh, w1h, in_b1, qkv, 3 * DMODEL);
    attention_tc_kernel<<<gATT, 256, ATTN_SMEM5>>>(qkv, bufA);

    // fused out_proj(L1) + in_proj(L2)
    h16_gemm_kernel<<<gQKV, 256, TCG_SMEM>>>(bufA, wcomb, bcomb, qkv, 3 * DMODEL);
    attention_tc_kernel<<<gATT, 256, ATTN_SMEM5>>>(qkv, bufA);

    // pool attention output directly; out_proj2 commutes with mean-pool
    pool_kernel<<<NUM_GRAPHS, DMODEL>>>(bufA, pooled);
    dim3 gP2(DMODEL / 128, NUM_GRAPHS / 128);
    gemm_tn_kernel<false><<<gP2, 256>>>(pooled, out_w2, out_b2, pooled2,
                                        NUM_GRAPHS, DMODEL, DMODEL);

    // readout MLP
    dim3 gR1(DMODEL / 128, NUM_GRAPHS / 128);
    gemm_tn_kernel<true><<<gR1, 256>>>(pooled2, r_w1, r_b1, r1, NUM_GRAPHS, DMODEL, DMODEL);
    dim3 gR2(1, NUM_GRAPHS / 128);
    gemm_tn_kernel<true><<<gR2, 256>>>(r1, r_w2, r_b2, r2, NUM_GRAPHS, 128, DMODEL);
    final_kernel<<<NUM_GRAPHS, 128>>>(r2, r_w3, r_b3, out);
}

// round 16
// speedup vs baseline: 1.0983x; 1.0507x over previous
#include <cuda_runtime.h>
#include <cuda_fp16.h>
#include <cstdint>
#include <math.h>

#define TOTAL_ATOMS 65536
#define NUM_GRAPHS  512
#define DMODEL      256
#define NHEAD       4
#define DHEAD       64
#define NMAX        160

// ---------------- scratch ----------------
__device__ __half g_qkv [ (size_t)TOTAL_ATOMS * 3 * DMODEL ];
__device__ __half g_bufA[ (size_t)TOTAL_ATOMS * DMODEL ];
__device__ __half g_xh  [ (size_t)TOTAL_ATOMS * DMODEL ];
__device__ __half g_w1h [ 3 * DMODEL * DMODEL ];
__device__ __half g_w2h [ 3 * DMODEL * DMODEL ];
__device__ __half g_wo1t[ DMODEL * DMODEL ];
__device__ __half g_wcomb[ 3 * DMODEL * DMODEL ];
__device__ float  g_bcomb[ 3 * DMODEL ];
__device__ float  g_zero256[ DMODEL ];
__device__ float g_pooled [ NUM_GRAPHS * DMODEL ];   // atomic sums
__device__ float g_poolm  [ NUM_GRAPHS * DMODEL ];   // means
__device__ float g_pooled2[ NUM_GRAPHS * DMODEL ];
__device__ float g_r1    [ NUM_GRAPHS * DMODEL ];
__device__ float g_r2    [ NUM_GRAPHS * 128 ];
__device__ int   g_start [ NUM_GRAPHS + 1 ];

// ---------------- per-graph start offsets ----------------
__global__ void compute_starts_kernel(const int* __restrict__ batch) {
    int i = blockIdx.x * blockDim.x + threadIdx.x;
    if (i >= TOTAL_ATOMS) return;
    if (i == 0) {
        g_start[batch[0]] = 0;
        g_start[NUM_GRAPHS] = TOTAL_ATOMS;
    } else if (batch[i] != batch[i - 1]) {
        g_start[batch[i]] = i;
    }
}

// ---------------- zero pooled sums ----------------
__global__ void zero_pool_kernel(float* __restrict__ ps) {
    ps[blockIdx.x * DMODEL + threadIdx.x] = 0.f;
}

// ---------------- pooled mean = sum / n ----------------
__global__ void pool_scale_kernel(const float* __restrict__ ps, float* __restrict__ pm) {
    int g = blockIdx.x, d = threadIdx.x;
    int n = g_start[g + 1] - g_start[g];
    pm[g * DMODEL + d] = ps[g * DMODEL + d] / (float)n;
}

// ---------------- fused fp32 -> fp16 convert ----------------
#define NX4 (TOTAL_ATOMS * DMODEL / 4)
#define NW4 (3 * DMODEL * DMODEL / 4)
__global__ void f2h_all_kernel(const float* __restrict__ x,
                               const float* __restrict__ w1,
                               const float* __restrict__ w2,
                               __half* __restrict__ xh,
                               __half* __restrict__ w1h,
                               __half* __restrict__ w2h) {
    int i = blockIdx.x * blockDim.x + threadIdx.x;
    const float* src;
    __half* dst;
    int off;
    if (i < NX4)                { src = x;  dst = xh;  off = i; }
    else if (i < NX4 + NW4)     { src = w1; dst = w1h; off = i - NX4; }
    else if (i < NX4 + 2 * NW4) { src = w2; dst = w2h; off = i - NX4 - NW4; }
    else return;
    float4 v = ((const float4*)src)[off];
    __half2* d = (__half2*)dst + off * 2;
    d[0] = __floats2half2_rn(v.x, v.y);
    d[1] = __floats2half2_rn(v.z, v.w);
}

// ---------------- transpose-convert ----------------
__global__ void transpose_h_kernel(const float* __restrict__ src, __half* __restrict__ dst) {
    __shared__ float tile[32][33];
    int bx = blockIdx.x * 32, by = blockIdx.y * 32;
    tile[threadIdx.y][threadIdx.x] = src[(by + threadIdx.y) * DMODEL + bx + threadIdx.x];
    __syncthreads();
    dst[(bx + threadIdx.y) * DMODEL + by + threadIdx.x] =
        __float2half(tile[threadIdx.x][threadIdx.y]);
}

// ---------------- bcomb ----------------
__global__ void bcomb_kernel(const float* __restrict__ w2, const float* __restrict__ bo1,
                             const float* __restrict__ bi2, float* __restrict__ bcomb) {
    int i = blockIdx.x;
    int t = threadIdx.x;
    float s = w2[i * DMODEL + t] * bo1[t] + w2[i * DMODEL + t + 128] * bo1[t + 128];
#pragma unroll
    for (int o = 16; o; o >>= 1) s += __shfl_xor_sync(0xffffffffu, s, o);
    __shared__ float red[4];
    if ((t & 31) == 0) red[t >> 5] = s;
    __syncthreads();
    if (t == 0) bcomb[i] = red[0] + red[1] + red[2] + red[3] + bi2[i];
}

// ---------------- asm helpers ----------------
__device__ __forceinline__ uint32_t smem_u32(const void* p) {
    uint32_t a;
    asm("{ .reg .u64 t; cvta.to.shared.u64 t, %1; cvt.u32.u64 %0, t; }" : "=r"(a) : "l"(p));
    return a;
}
__device__ __forceinline__ void mma_f16(float* d, const uint32_t* a, const uint32_t* b) {
    asm volatile(
        "mma.sync.aligned.m16n8k16.row.col.f32.f16.f16.f32 "
        "{%0,%1,%2,%3}, {%4,%5,%6,%7}, {%8,%9}, {%0,%1,%2,%3};"
        : "+f"(d[0]), "+f"(d[1]), "+f"(d[2]), "+f"(d[3])
        : "r"(a[0]), "r"(a[1]), "r"(a[2]), "r"(a[3]), "r"(b[0]), "r"(b[1]));
}
#define LDSM_X4(r0, r1, r2, r3, addr) \
    asm volatile("ldmatrix.sync.aligned.m8n8.x4.shared.b16 {%0,%1,%2,%3}, [%4];" \
        : "=r"(r0), "=r"(r1), "=r"(r2), "=r"(r3) : "r"(addr))
#define LDSM_X2(r0, r1, addr) \
    asm volatile("ldmatrix.sync.aligned.m8n8.x2.shared.b16 {%0,%1}, [%2];" \
        : "=r"(r0), "=r"(r1) : "r"(addr))
#define CP_ASYNC16(dst, src) \
    asm volatile("cp.async.cg.shared.global [%0], [%1], 16;" :: "r"(dst), "l"(src))
#define CP_COMMIT() asm volatile("cp.async.commit_group;" ::: "memory")
#define CP_WAIT2()  asm volatile("cp.async.wait_group 2;" ::: "memory")

// ================= fp16 GEMM, 128x128 tile =================
#define STAGE_BYTES 20480
#define TCG_SMEM (4 * STAGE_BYTES)

__global__ void __launch_bounds__(256, 2)
h16_gemm_kernel(const __half* __restrict__ A, const __half* __restrict__ B,
                const float* __restrict__ bias, __half* __restrict__ C, int Ntot) {
    extern __shared__ char smem[];
    uint32_t sbase = smem_u32(smem);
    const int K = DMODEL;

    int tid   = threadIdx.x;
    int lane  = tid & 31;
    int wid   = tid >> 5;
    int warpM = wid & 1;
    int warpN = wid >> 1;
    int m0 = blockIdx.y * 128;
    int n0 = blockIdx.x * 128;

    const __half* Ab = A + (size_t)m0 * K;
    const __half* Bb = B + (size_t)n0 * K;

    int ar0 = tid >> 2;
    int aq  = tid & 3;
    int ar1 = ar0 + 64;
    uint32_t adst0 = ar0 * 80 + aq * 16;
    uint32_t adst1 = ar1 * 80 + aq * 16;
    const __half* asrc0 = Ab + (size_t)ar0 * K + aq * 8;
    const __half* asrc1 = Ab + (size_t)ar1 * K + aq * 8;
    const __half* bsrc0 = Bb + (size_t)ar0 * K + aq * 8;
    const __half* bsrc1 = Bb + (size_t)ar1 * K + aq * 8;

    int lr  = lane & 7;
    int seg = lane >> 3;
    uint32_t aoff = (uint32_t)((warpM * 64 + lr + (seg & 1) * 8) * 80 + (seg >> 1) * 16);
    uint32_t boff = (uint32_t)(10240 + (warpN * 32 + lr) * 80 + (seg & 1) * 16);

    float acc[4][4][4];
#pragma unroll
    for (int mt = 0; mt < 4; mt++)
#pragma unroll
        for (int nt = 0; nt < 4; nt++)
#pragma unroll
            for (int j = 0; j < 4; j++) acc[mt][nt][j] = 0.f;

#pragma unroll
    for (int s = 0; s < 3; s++) {
        uint32_t stg = sbase + s * STAGE_BYTES;
        int k0 = s * 32;
        CP_ASYNC16(stg + adst0,         asrc0 + k0);
        CP_ASYNC16(stg + adst1,         asrc1 + k0);
        CP_ASYNC16(stg + 10240 + adst0, bsrc0 + k0);
        CP_ASYNC16(stg + 10240 + adst1, bsrc1 + k0);
        CP_COMMIT();
    }

#pragma unroll 1
    for (int ch = 0; ch < 8; ch++) {
        CP_WAIT2();
        __syncthreads();

        if (ch + 3 < 8) {
            uint32_t stg = sbase + ((ch + 3) & 3) * STAGE_BYTES;
            int k0 = (ch + 3) * 32;
            CP_ASYNC16(stg + adst0,         asrc0 + k0);
            CP_ASYNC16(stg + adst1,         asrc1 + k0);
            CP_ASYNC16(stg + 10240 + adst0, bsrc0 + k0);
            CP_ASYNC16(stg + 10240 + adst1, bsrc1 + k0);
        }
        CP_COMMIT();

        uint32_t st = sbase + (ch & 3) * STAGE_BYTES;

#pragma unroll
        for (int ks = 0; ks < 2; ks++) {
            uint32_t af[4][4];
#pragma unroll
            for (int mt = 0; mt < 4; mt++)
                LDSM_X4(af[mt][0], af[mt][1], af[mt][2], af[mt][3],
                        st + aoff + mt * 1280 + ks * 32);
            uint32_t bf[4][2];
#pragma unroll
            for (int nt = 0; nt < 4; nt++)
                LDSM_X2(bf[nt][0], bf[nt][1],
                        st + boff + nt * 640 + ks * 32);
#pragma unroll
            for (int mt = 0; mt < 4; mt++)
#pragma unroll
                for (int nt = 0; nt < 4; nt++)
                    mma_f16(acc[mt][nt], af[mt], bf[nt]);
        }
    }

    int r  = lane >> 2;
    int c2 = (lane & 3) * 2;
#pragma unroll
    for (int nt = 0; nt < 4; nt++) {
        int col = n0 + warpN * 32 + nt * 8 + c2;
        float bx = bias[col], by = bias[col + 1];
#pragma unroll
        for (int mt = 0; mt < 4; mt++) {
            int row = m0 + warpM * 64 + mt * 16 + r;
            __half2* p0 = (__half2*)(C + (size_t)row * Ntot + col);
            __half2* p1 = (__half2*)(C + (size_t)(row + 8) * Ntot + col);
            *p0 = __floats2half2_rn(acc[mt][nt][0] + bx, acc[mt][nt][1] + by);
            *p1 = __floats2half2_rn(acc[mt][nt][2] + bx, acc[mt][nt][3] + by);
        }
    }
}

// ---------------- fp32 GEMM (small readout layers) ----------------
template <bool RELU>
__global__ void __launch_bounds__(256)
gemm_tn_kernel(const float* __restrict__ A, const float* __restrict__ B,
               const float* __restrict__ bias, float* __restrict__ C,
               int M, int N, int K) {
    const int BM = 128, BN = 128, BK = 8;
    __shared__ float As[BK][BM];
    __shared__ float Bs[BK][BN];

    int tid  = threadIdx.x;
    int brow = blockIdx.y;
    int bcol = blockIdx.x;

    const float* Ab = A + (size_t)brow * BM * K;
    const float* Bb = B + (size_t)bcol * BN * K;

    int lr = tid >> 1;
    int lc = (tid & 1) * 4;
    int ty = tid >> 4;
    int tx = tid & 15;

    float acc[8][8];
#pragma unroll
    for (int i = 0; i < 8; i++)
#pragma unroll
        for (int j = 0; j < 8; j++) acc[i][j] = 0.f;

    for (int k0 = 0; k0 < K; k0 += BK) {
        float4 a = *(const float4*)(Ab + (size_t)lr * K + k0 + lc);
        float4 b = *(const float4*)(Bb + (size_t)lr * K + k0 + lc);
        As[lc + 0][lr] = a.x; As[lc + 1][lr] = a.y;
        As[lc + 2][lr] = a.z; As[lc + 3][lr] = a.w;
        Bs[lc + 0][lr] = b.x; Bs[lc + 1][lr] = b.y;
        Bs[lc + 2][lr] = b.z; Bs[lc + 3][lr] = b.w;
        __syncthreads();
#pragma unroll
        for (int k = 0; k < BK; k++) {
            float4 a0 = *(const float4*)(&As[k][ty * 4]);
            float4 a1 = *(const float4*)(&As[k][64 + ty * 4]);
            float4 b0 = *(const float4*)(&Bs[k][tx * 4]);
            float4 b1 = *(const float4*)(&Bs[k][64 + tx * 4]);
            float ra[8] = {a0.x, a0.y, a0.z, a0.w, a1.x, a1.y, a1.z, a1.w};
            float rb[8] = {b0.x, b0.y, b0.z, b0.w, b1.x, b1.y, b1.z, b1.w};
#pragma unroll
            for (int i = 0; i < 8; i++)
#pragma unroll
                for (int j = 0; j < 8; j++) acc[i][j] += ra[i] * rb[j];
        }
        __syncthreads();
    }

    float4 bb0 = *(const float4*)(bias + bcol * BN + tx * 4);
    float4 bb1 = *(const float4*)(bias + bcol * BN + 64 + tx * 4);
    float bv[8] = {bb0.x, bb0.y, bb0.z, bb0.w, bb1.x, bb1.y, bb1.z, bb1.w};

#pragma unroll
    for (int i = 0; i < 8; i++) {
        int row = brow * BM + (i < 4 ? ty * 4 + i : 64 + ty * 4 + (i - 4));
        float* crow = C + (size_t)row * N + bcol * BN;
        float v[8];
#pragma unroll
        for (int j = 0; j < 8; j++) {
            float t = acc[i][j] + bv[j];
            if (RELU) t = fmaxf(t, 0.f);
            v[j] = t;
        }
        *(float4*)(crow + tx * 4)      = make_float4(v[0], v[1], v[2], v[3]);
        *(float4*)(crow + 64 + tx * 4) = make_float4(v[4], v[5], v[6], v[7]);
    }
}

// ======== all-fp16 attention, register-resident P (FA2 trick) ========
// Qh/Kh: fp16 [NMAX][64] @144B rows. Vt: fp16 [64][NMAX] @336B rows.
// S D-frags ARE PV A-frags after half2 packing: no P smem round-trip.
// POOL=true: accumulate column sums into pooled[] (atomicAdd), no out write.
#define VT_W 84
#define SM_QH 0
#define SM_KH (NMAX * 144)
#define SM_VT (2 * NMAX * 144)
#define ATTN_SMEM6 (SM_VT + 64 * VT_W * 4)   // 67584 B

template <bool POOL>
__global__ void __launch_bounds__(256, 2)
attention_tc_kernel(const __half* __restrict__ qkv, __half* __restrict__ out,
                    float* __restrict__ pooled) {
    extern __shared__ char sm[];
    uint32_t sb = smem_u32(sm);
    uint32_t* Qh = (uint32_t*)(sm + SM_QH);
    uint32_t* Kh = (uint32_t*)(sm + SM_KH);
    __half*   Vt_h = (__half*)(sm + SM_VT);

    int g = blockIdx.x;
    int h = blockIdx.y;
    int s0 = g_start[g];
    int n  = g_start[g + 1] - s0;

    int tid  = threadIdx.x;
    int lane = tid & 31;
    int warp = tid >> 5;

    for (int idx = tid; idx < NMAX * 8; idx += 256) {
        int r = idx >> 3, q8 = idx & 7;
        uint4 hq = make_uint4(0, 0, 0, 0), hk = hq, hv = hq;
        if (r < n) {
            const __half* base = qkv + (size_t)(s0 + r) * (3 * DMODEL) + h * DHEAD + q8 * 8;
            hq = *(const uint4*)(base);
            hk = *(const uint4*)(base + DMODEL);
            hv = *(const uint4*)(base + 2 * DMODEL);
        }
        *(uint4*)((char*)Qh + r * 144 + q8 * 16) = hq;
        *(uint4*)((char*)Kh + r * 144 + q8 * 16) = hk;
        const __half* hv_h = (const __half*)&hv;
#pragma unroll
        for (int j = 0; j < 8; j++)
            Vt_h[(q8 * 8 + j) * (2 * VT_W) + r] = hv_h[j];
    }
    __syncthreads();

    int ntiles = (n + 15) >> 4;
    int nfc    = (n + 7) >> 3;
    int r = lane >> 2;
    int c = lane & 3;
    int lr  = lane & 7;
    int seg = lane >> 3;

#pragma unroll 1
    for (int mt = warp; mt < ntiles; mt += 8) {
        int m0 = mt * 16;

        uint32_t q_addr = sb + SM_QH + (m0 + lr + (seg & 1) * 8) * 144 + (seg >> 1) * 16;
        uint32_t aq[4][4];
#pragma unroll
        for (int ks = 0; ks < 4; ks++)
            LDSM_X4(aq[ks][0], aq[ks][1], aq[ks][2], aq[ks][3], q_addr + ks * 32);

        uint32_t k_addr = sb + SM_KH + lr * 144 + (seg & 1) * 16;
        float s[20][4];
#pragma unroll
        for (int nf = 0; nf < 20; nf++) {
            s[nf][0] = 0.f; s[nf][1] = 0.f; s[nf][2] = 0.f; s[nf][3] = 0.f;
        }
#pragma unroll
        for (int nf = 0; nf < 20; nf++) {
            if (nf >= nfc) continue;
            uint32_t ka = k_addr + nf * (8 * 144);
#pragma unroll
            for (int ks = 0; ks < 4; ks++) {
                uint32_t bf[2];
                LDSM_X2(bf[0], bf[1], ka + ks * 32);
                mma_f16(s[nf], aq[ks], bf);
            }
        }

        float mx0 = -1e30f, mx1 = -1e30f;
#pragma unroll
        for (int nf = 0; nf < 20; nf++) {
            if (nf >= nfc) continue;
            int col0 = nf * 8 + 2 * c;
            s[nf][0] = (col0     < n) ? s[nf][0] * 0.125f : -1e30f;
            s[nf][1] = (col0 + 1 < n) ? s[nf][1] * 0.125f : -1e30f;
            s[nf][2] = (col0     < n) ? s[nf][2] * 0.125f : -1e30f;
            s[nf][3] = (col0 + 1 < n) ? s[nf][3] * 0.125f : -1e30f;
            mx0 = fmaxf(mx0, fmaxf(s[nf][0], s[nf][1]));
            mx1 = fmaxf(mx1, fmaxf(s[nf][2], s[nf][3]));
        }
        mx0 = fmaxf(mx0, __shfl_xor_sync(0xffffffffu, mx0, 1));
        mx0 = fmaxf(mx0, __shfl_xor_sync(0xffffffffu, mx0, 2));
        mx1 = fmaxf(mx1, __shfl_xor_sync(0xffffffffu, mx1, 1));
        mx1 = fmaxf(mx1, __shfl_xor_sync(0xffffffffu, mx1, 2));

        float sum0 = 0.f, sum1 = 0.f;
#pragma unroll
        for (int nf = 0; nf < 20; nf++) {
            if (nf >= nfc) continue;
            float p0 = __expf(s[nf][0] - mx0);
            float p1 = __expf(s[nf][1] - mx0);
            float p2 = __expf(s[nf][2] - mx1);
            float p3 = __expf(s[nf][3] - mx1);
            s[nf][0] = p0; s[nf][1] = p1; s[nf][2] = p2; s[nf][3] = p3;
            sum0 += p0 + p1;
            sum1 += p2 + p3;
        }
        sum0 += __shfl_xor_sync(0xffffffffu, sum0, 1);
        sum0 += __shfl_xor_sync(0xffffffffu, sum0, 2);
        sum1 += __shfl_xor_sync(0xffffffffu, sum1, 1);
        sum1 += __shfl_xor_sync(0xffffffffu, sum1, 2);
        float inv0 = 1.f / sum0;
        float inv1 = 1.f / sum1;

        // ---- O = P V with P packed directly from S registers ----
        uint32_t v_addr = sb + SM_VT + lr * (VT_W * 4) + (seg & 1) * 16;
        float o[8][4];
#pragma unroll
        for (int nd = 0; nd < 8; nd++) {
            o[nd][0] = 0.f; o[nd][1] = 0.f; o[nd][2] = 0.f; o[nd][3] = 0.f;
        }
#pragma unroll
        for (int ks = 0; ks < 10; ks++) {
            if (ks >= ntiles) continue;
            __half2 h0 = __floats2half2_rn(s[2 * ks][0],     s[2 * ks][1]);
            __half2 h1 = __floats2half2_rn(s[2 * ks][2],     s[2 * ks][3]);
            __half2 h2v = __floats2half2_rn(s[2 * ks + 1][0], s[2 * ks + 1][1]);
            __half2 h3 = __floats2half2_rn(s[2 * ks + 1][2], s[2 * ks + 1][3]);
            uint32_t ap[4];
            ap[0] = *(uint32_t*)&h0;
            ap[1] = *(uint32_t*)&h1;
            ap[2] = *(uint32_t*)&h2v;
            ap[3] = *(uint32_t*)&h3;
#pragma unroll
            for (int nd = 0; nd < 8; nd++) {
                uint32_t bf[2];
                LDSM_X2(bf[0], bf[1], v_addr + nd * (8 * VT_W * 4) + ks * 32);
                mma_f16(o[nd], ap, bf);
            }
        }

        int row0 = m0 + r, row1 = m0 + r + 8;
        if (POOL) {
            float* pg = pooled + g * DMODEL + h * DHEAD;
#pragma unroll
            for (int nd = 0; nd < 8; nd++) {
                float v0 = (row0 < n ? o[nd][0] * inv0 : 0.f) + (row1 < n ? o[nd][2] * inv1 : 0.f);
                float v1 = (row0 < n ? o[nd][1] * inv0 : 0.f) + (row1 < n ? o[nd][3] * inv1 : 0.f);
                v0 += __shfl_xor_sync(0xffffffffu, v0, 4);
                v1 += __shfl_xor_sync(0xffffffffu, v1, 4);
                v0 += __shfl_xor_sync(0xffffffffu, v0, 8);
                v1 += __shfl_xor_sync(0xffffffffu, v1, 8);
                v0 += __shfl_xor_sync(0xffffffffu, v0, 16);
                v1 += __shfl_xor_sync(0xffffffffu, v1, 16);
                if (r == 0) {
                    atomicAdd(pg + nd * 8 + 2 * c,     v0);
                    atomicAdd(pg + nd * 8 + 2 * c + 1, v1);
                }
            }
        } else {
#pragma unroll
            for (int nd = 0; nd < 8; nd++) {
                int col = h * DHEAD + nd * 8 + 2 * c;
                if (row0 < n)
                    *(__half2*)(out + (size_t)(s0 + row0) * DMODEL + col) =
                        __floats2half2_rn(o[nd][0] * inv0, o[nd][1] * inv0);
                if (row1 < n)
                    *(__half2*)(out + (size_t)(s0 + row1) * DMODEL + col) =
                        __floats2half2_rn(o[nd][2] * inv1, o[nd][3] * inv1);
            }
        }
        __syncwarp();
    }
}

// ---------------- final 128 -> 1 dot ----------------
__global__ void final_kernel(const float* __restrict__ h2, const float* __restrict__ w,
                             const float* __restrict__ b, float* __restrict__ out) {
    __shared__ float red[128];
    int g = blockIdx.x;
    int t = threadIdx.x;
    red[t] = h2[g * 128 + t] * w[t];
    __syncthreads();
    for (int s = 64; s; s >>= 1) {
        if (t < s) red[t] += red[t + s];
        __syncthreads();
    }
    if (t == 0) out[g] = red[0] + b[0];
}

// ---------------- launch ----------------
extern "C" void kernel_launch(void* const* d_in, const int* in_sizes, int n_in,
                              void* d_out, int out_size) {
    const float* x      = (const float*)d_in[0];
    const int*   batch  = (const int*)  d_in[1];
    const float* in_w1  = (const float*)d_in[2];
    const float* in_b1  = (const float*)d_in[3];
    const float* out_w1 = (const float*)d_in[4];
    const float* out_b1 = (const float*)d_in[5];
    const float* in_w2  = (const float*)d_in[6];
    const float* in_b2  = (const float*)d_in[7];
    const float* out_w2 = (const float*)d_in[8];
    const float* out_b2 = (const float*)d_in[9];
    const float* r_w1   = (const float*)d_in[10];
    const float* r_b1   = (const float*)d_in[11];
    const float* r_w2   = (const float*)d_in[12];
    const float* r_b2   = (const float*)d_in[13];
    const float* r_w3   = (const float*)d_in[14];
    const float* r_b3   = (const float*)d_in[15];
    float* out = (float*)d_out;

    __half *qkv, *bufA, *xh, *w1h, *w2h, *wo1t, *wcomb;
    float *pooled, *poolm, *pooled2, *r1, *r2, *bcomb, *zero256;
    cudaGetSymbolAddress((void**)&qkv,    g_qkv);
    cudaGetSymbolAddress((void**)&bufA,   g_bufA);
    cudaGetSymbolAddress((void**)&xh,     g_xh);
    cudaGetSymbolAddress((void**)&w1h,    g_w1h);
    cudaGetSymbolAddress((void**)&w2h,    g_w2h);
    cudaGetSymbolAddress((void**)&wo1t,   g_wo1t);
    cudaGetSymbolAddress((void**)&wcomb,  g_wcomb);
    cudaGetSymbolAddress((void**)&bcomb,  g_bcomb);
    cudaGetSymbolAddress((void**)&zero256, g_zero256);
    cudaGetSymbolAddress((void**)&pooled, g_pooled);
    cudaGetSymbolAddress((void**)&poolm,  g_poolm);
    cudaGetSymbolAddress((void**)&pooled2, g_pooled2);
    cudaGetSymbolAddress((void**)&r1,     g_r1);
    cudaGetSymbolAddress((void**)&r2,     g_r2);

    cudaFuncSetAttribute(attention_tc_kernel<false>,
                         cudaFuncAttributeMaxDynamicSharedMemorySize, ATTN_SMEM6);
    cudaFuncSetAttribute(attention_tc_kernel<true>,
                         cudaFuncAttributeMaxDynamicSharedMemorySize, ATTN_SMEM6);
    cudaFuncSetAttribute(h16_gemm_kernel,
                         cudaFuncAttributeMaxDynamicSharedMemorySize, TCG_SMEM);

    compute_starts_kernel<<<(TOTAL_ATOMS + 255) / 256, 256>>>(batch);
    zero_pool_kernel<<<NUM_GRAPHS, DMODEL>>>(pooled);

    int totF4 = NX4 + 2 * NW4;
    f2h_all_kernel<<<(totF4 + 255) / 256, 256>>>(x, in_w1, in_w2, xh, w1h, w2h);

    // ---- precompute fused layer weights ----
    dim3 tgrid(8, 8), tblk(32, 32);
    transpose_h_kernel<<<tgrid, tblk>>>(out_w1, wo1t);
    dim3 gPC(2, 6);
    h16_gemm_kernel<<<gPC, 256, TCG_SMEM>>>(w2h, wo1t, zero256, wcomb, DMODEL);
    bcomb_kernel<<<3 * DMODEL, 128>>>(in_w2, out_b1, in_b2, bcomb);

    dim3 gQKV(3 * DMODEL / 128, TOTAL_ATOMS / 128);
    dim3 gATT(NUM_GRAPHS, NHEAD);

    // layer 1: in_proj + attention
    h16_gemm_kernel<<<gQKV, 256, TCG_SMEM>>>(xh, w1h, in_b1, qkv, 3 * DMODEL);
    attention_tc_kernel<false><<<gATT, 256, ATTN_SMEM6>>>(qkv, bufA, pooled);

    // fused out_proj(L1) + in_proj(L2)
    h16_gemm_kernel<<<gQKV, 256, TCG_SMEM>>>(bufA, wcomb, bcomb, qkv, 3 * DMODEL);
    // attention 2 with fused mean-pool accumulation
    attention_tc_kernel<true><<<gATT, 256, ATTN_SMEM6>>>(qkv, bufA, pooled);

    // mean + out_proj2 (commuted past pool) + readout
    pool_scale_kernel<<<NUM_GRAPHS, DMODEL>>>(pooled, poolm);
    dim3 gP2(DMODEL / 128, NUM_GRAPHS / 128);
    gemm_tn_kernel<false><<<gP2, 256>>>(poolm, out_w2, out_b2, pooled2,
                                        NUM_GRAPHS, DMODEL, DMODEL);
    dim3 gR1(DMODEL / 128, NUM_GRAPHS / 128);
    gemm_tn_kernel<true><<<gR1, 256>>>(pooled2, r_w1, r_b1, r1, NUM_GRAPHS, DMODEL, DMODEL);
    dim3 gR2(1, NUM_GRAPHS / 128);
    gemm_tn_kernel<true><<<gR2, 256>>>(r1, r_w2, r_b2, r2, NUM_GRAPHS, 128, DMODEL);
    final_kernel<<<NUM_GRAPHS, 128>>>(r2, r_w3, r_b3, out);
}

// round 17
// speedup vs baseline: 1.2564x; 1.1440x over previous
#include <cuda_runtime.h>
#include <cuda_fp16.h>
#include <cstdint>
#include <math.h>

#define TOTAL_ATOMS 65536
#define NUM_GRAPHS  512
#define DMODEL      256
#define NHEAD       4
#define DHEAD       64
#define NMAX        160

// ---------------- scratch ----------------
__device__ __half g_qkv [ (size_t)TOTAL_ATOMS * 3 * DMODEL ];
__device__ __half g_bufA[ (size_t)TOTAL_ATOMS * DMODEL ];
__device__ __half g_xh  [ (size_t)TOTAL_ATOMS * DMODEL ];
__device__ __half g_w1h [ 3 * DMODEL * DMODEL ];
__device__ __half g_w2h [ 3 * DMODEL * DMODEL ];
__device__ __half g_wo1t[ DMODEL * DMODEL ];
__device__ __half g_wcomb[ 3 * DMODEL * DMODEL ];
__device__ float  g_bcomb[ 3 * DMODEL ];
__device__ float  g_zero256[ DMODEL ];
__device__ float g_pooled [ NUM_GRAPHS * DMODEL ];   // atomic sums
__device__ int   g_start [ NUM_GRAPHS + 1 ];

// ---------------- per-graph start offsets ----------------
__global__ void compute_starts_kernel(const int* __restrict__ batch) {
    int i = blockIdx.x * blockDim.x + threadIdx.x;
    if (i >= TOTAL_ATOMS) return;
    if (i == 0) {
        g_start[batch[0]] = 0;
        g_start[NUM_GRAPHS] = TOTAL_ATOMS;
    } else if (batch[i] != batch[i - 1]) {
        g_start[batch[i]] = i;
    }
}

// ---------------- fused fp32->fp16 convert + pooled zeroing ----------------
#define NX4 (TOTAL_ATOMS * DMODEL / 4)
#define NW4 (3 * DMODEL * DMODEL / 4)
#define NP4 (NUM_GRAPHS * DMODEL / 4)
__global__ void f2h_all_kernel(const float* __restrict__ x,
                               const float* __restrict__ w1,
                               const float* __restrict__ w2,
                               __half* __restrict__ xh,
                               __half* __restrict__ w1h,
                               __half* __restrict__ w2h,
                               float* __restrict__ pooled) {
    int i = blockIdx.x * blockDim.x + threadIdx.x;
    const float* src;
    __half* dst;
    int off;
    if (i < NX4)                { src = x;  dst = xh;  off = i; }
    else if (i < NX4 + NW4)     { src = w1; dst = w1h; off = i - NX4; }
    else if (i < NX4 + 2 * NW4) { src = w2; dst = w2h; off = i - NX4 - NW4; }
    else if (i < NX4 + 2 * NW4 + NP4) {
        ((float4*)pooled)[i - NX4 - 2 * NW4] = make_float4(0.f, 0.f, 0.f, 0.f);
        return;
    }
    else return;
    float4 v = ((const float4*)src)[off];
    __half2* d = (__half2*)dst + off * 2;
    d[0] = __floats2half2_rn(v.x, v.y);
    d[1] = __floats2half2_rn(v.z, v.w);
}

// ---------------- transpose-convert ----------------
__global__ void transpose_h_kernel(const float* __restrict__ src, __half* __restrict__ dst) {
    __shared__ float tile[32][33];
    int bx = blockIdx.x * 32, by = blockIdx.y * 32;
    tile[threadIdx.y][threadIdx.x] = src[(by + threadIdx.y) * DMODEL + bx + threadIdx.x];
    __syncthreads();
    dst[(bx + threadIdx.y) * DMODEL + by + threadIdx.x] =
        __float2half(tile[threadIdx.x][threadIdx.y]);
}

// ---------------- bcomb ----------------
__global__ void bcomb_kernel(const float* __restrict__ w2, const float* __restrict__ bo1,
                             const float* __restrict__ bi2, float* __restrict__ bcomb) {
    int i = blockIdx.x;
    int t = threadIdx.x;
    float s = w2[i * DMODEL + t] * bo1[t] + w2[i * DMODEL + t + 128] * bo1[t + 128];
#pragma unroll
    for (int o = 16; o; o >>= 1) s += __shfl_xor_sync(0xffffffffu, s, o);
    __shared__ float red[4];
    if ((t & 31) == 0) red[t >> 5] = s;
    __syncthreads();
    if (t == 0) bcomb[i] = red[0] + red[1] + red[2] + red[3] + bi2[i];
}

// ---------------- asm helpers ----------------
__device__ __forceinline__ uint32_t smem_u32(const void* p) {
    uint32_t a;
    asm("{ .reg .u64 t; cvta.to.shared.u64 t, %1; cvt.u32.u64 %0, t; }" : "=r"(a) : "l"(p));
    return a;
}
__device__ __forceinline__ void mma_f16(float* d, const uint32_t* a, const uint32_t* b) {
    asm volatile(
        "mma.sync.aligned.m16n8k16.row.col.f32.f16.f16.f32 "
        "{%0,%1,%2,%3}, {%4,%5,%6,%7}, {%8,%9}, {%0,%1,%2,%3};"
        : "+f"(d[0]), "+f"(d[1]), "+f"(d[2]), "+f"(d[3])
        : "r"(a[0]), "r"(a[1]), "r"(a[2]), "r"(a[3]), "r"(b[0]), "r"(b[1]));
}
#define LDSM_X4(r0, r1, r2, r3, addr) \
    asm volatile("ldmatrix.sync.aligned.m8n8.x4.shared.b16 {%0,%1,%2,%3}, [%4];" \
        : "=r"(r0), "=r"(r1), "=r"(r2), "=r"(r3) : "r"(addr))
#define LDSM_X2(r0, r1, addr) \
    asm volatile("ldmatrix.sync.aligned.m8n8.x2.shared.b16 {%0,%1}, [%2];" \
        : "=r"(r0), "=r"(r1) : "r"(addr))
#define LDSM_X2T(r0, r1, addr) \
    asm volatile("ldmatrix.sync.aligned.m8n8.x2.trans.shared.b16 {%0,%1}, [%2];" \
        : "=r"(r0), "=r"(r1) : "r"(addr))
#define CP_ASYNC16(dst, src) \
    asm volatile("cp.async.cg.shared.global [%0], [%1], 16;" :: "r"(dst), "l"(src))
#define CP_COMMIT() asm volatile("cp.async.commit_group;" ::: "memory")
#define CP_WAIT2()  asm volatile("cp.async.wait_group 2;" ::: "memory")

// ================= fp16 GEMM, 128x128 tile =================
#define STAGE_BYTES 20480
#define TCG_SMEM (4 * STAGE_BYTES)

__global__ void __launch_bounds__(256, 2)
h16_gemm_kernel(const __half* __restrict__ A, const __half* __restrict__ B,
                const float* __restrict__ bias, __half* __restrict__ C, int Ntot) {
    extern __shared__ char smem[];
    uint32_t sbase = smem_u32(smem);
    const int K = DMODEL;

    int tid   = threadIdx.x;
    int lane  = tid & 31;
    int wid   = tid >> 5;
    int warpM = wid & 1;
    int warpN = wid >> 1;
    int m0 = blockIdx.y * 128;
    int n0 = blockIdx.x * 128;

    const __half* Ab = A + (size_t)m0 * K;
    const __half* Bb = B + (size_t)n0 * K;

    int ar0 = tid >> 2;
    int aq  = tid & 3;
    int ar1 = ar0 + 64;
    uint32_t adst0 = ar0 * 80 + aq * 16;
    uint32_t adst1 = ar1 * 80 + aq * 16;
    const __half* asrc0 = Ab + (size_t)ar0 * K + aq * 8;
    const __half* asrc1 = Ab + (size_t)ar1 * K + aq * 8;
    const __half* bsrc0 = Bb + (size_t)ar0 * K + aq * 8;
    const __half* bsrc1 = Bb + (size_t)ar1 * K + aq * 8;

    int lr  = lane & 7;
    int seg = lane >> 3;
    uint32_t aoff = (uint32_t)((warpM * 64 + lr + (seg & 1) * 8) * 80 + (seg >> 1) * 16);
    uint32_t boff = (uint32_t)(10240 + (warpN * 32 + lr) * 80 + (seg & 1) * 16);

    float acc[4][4][4];
#pragma unroll
    for (int mt = 0; mt < 4; mt++)
#pragma unroll
        for (int nt = 0; nt < 4; nt++)
#pragma unroll
            for (int j = 0; j < 4; j++) acc[mt][nt][j] = 0.f;

#pragma unroll
    for (int s = 0; s < 3; s++) {
        uint32_t stg = sbase + s * STAGE_BYTES;
        int k0 = s * 32;
        CP_ASYNC16(stg + adst0,         asrc0 + k0);
        CP_ASYNC16(stg + adst1,         asrc1 + k0);
        CP_ASYNC16(stg + 10240 + adst0, bsrc0 + k0);
        CP_ASYNC16(stg + 10240 + adst1, bsrc1 + k0);
        CP_COMMIT();
    }

#pragma unroll 1
    for (int ch = 0; ch < 8; ch++) {
        CP_WAIT2();
        __syncthreads();

        if (ch + 3 < 8) {
            uint32_t stg = sbase + ((ch + 3) & 3) * STAGE_BYTES;
            int k0 = (ch + 3) * 32;
            CP_ASYNC16(stg + adst0,         asrc0 + k0);
            CP_ASYNC16(stg + adst1,         asrc1 + k0);
            CP_ASYNC16(stg + 10240 + adst0, bsrc0 + k0);
            CP_ASYNC16(stg + 10240 + adst1, bsrc1 + k0);
        }
        CP_COMMIT();

        uint32_t st = sbase + (ch & 3) * STAGE_BYTES;

#pragma unroll
        for (int ks = 0; ks < 2; ks++) {
            uint32_t af[4][4];
#pragma unroll
            for (int mt = 0; mt < 4; mt++)
                LDSM_X4(af[mt][0], af[mt][1], af[mt][2], af[mt][3],
                        st + aoff + mt * 1280 + ks * 32);
            uint32_t bf[4][2];
#pragma unroll
            for (int nt = 0; nt < 4; nt++)
                LDSM_X2(bf[nt][0], bf[nt][1],
                        st + boff + nt * 640 + ks * 32);
#pragma unroll
            for (int mt = 0; mt < 4; mt++)
#pragma unroll
                for (int nt = 0; nt < 4; nt++)
                    mma_f16(acc[mt][nt], af[mt], bf[nt]);
        }
    }

    int r  = lane >> 2;
    int c2 = (lane & 3) * 2;
#pragma unroll
    for (int nt = 0; nt < 4; nt++) {
        int col = n0 + warpN * 32 + nt * 8 + c2;
        float bx = bias[col], by = bias[col + 1];
#pragma unroll
        for (int mt = 0; mt < 4; mt++) {
            int row = m0 + warpM * 64 + mt * 16 + r;
            __half2* p0 = (__half2*)(C + (size_t)row * Ntot + col);
            __half2* p1 = (__half2*)(C + (size_t)(row + 8) * Ntot + col);
            *p0 = __floats2half2_rn(acc[mt][nt][0] + bx, acc[mt][nt][1] + by);
            *p1 = __floats2half2_rn(acc[mt][nt][2] + bx, acc[mt][nt][3] + by);
        }
    }
}

// ======== all-fp16 attention, register P + ldmatrix.trans V ========
// Qh/Kh/Vh: fp16 [NMAX][64] @144B rows (uniform uint4 staging).
// V B-frags loaded with ldmatrix.x2.trans straight from row-major V.
#define SM_QH 0
#define SM_KH (NMAX * 144)
#define SM_V  (2 * NMAX * 144)
#define ATTN_SMEM7 (3 * NMAX * 144)   // 69120 B

template <bool POOL>
__global__ void __launch_bounds__(256, 2)
attention_tc_kernel(const __half* __restrict__ qkv, __half* __restrict__ out,
                    float* __restrict__ pooled) {
    extern __shared__ char sm[];
    uint32_t sb = smem_u32(sm);
    char* Qh = sm + SM_QH;
    char* Kh = sm + SM_KH;
    char* Vh = sm + SM_V;

    int g = blockIdx.x;
    int h = blockIdx.y;
    int s0 = g_start[g];
    int n  = g_start[g + 1] - s0;

    int tid  = threadIdx.x;
    int lane = tid & 31;
    int warp = tid >> 5;

    for (int idx = tid; idx < NMAX * 8; idx += 256) {
        int r = idx >> 3, q8 = idx & 7;
        uint4 hq = make_uint4(0, 0, 0, 0), hk = hq, hv = hq;
        if (r < n) {
            const __half* base = qkv + (size_t)(s0 + r) * (3 * DMODEL) + h * DHEAD + q8 * 8;
            hq = *(const uint4*)(base);
            hk = *(const uint4*)(base + DMODEL);
            hv = *(const uint4*)(base + 2 * DMODEL);
        }
        *(uint4*)(Qh + r * 144 + q8 * 16) = hq;
        *(uint4*)(Kh + r * 144 + q8 * 16) = hk;
        *(uint4*)(Vh + r * 144 + q8 * 16) = hv;
    }
    __syncthreads();

    int ntiles = (n + 15) >> 4;
    int nfc    = (n + 7) >> 3;
    int r = lane >> 2;
    int c = lane & 3;
    int lr  = lane & 7;
    int seg = lane >> 3;

#pragma unroll 1
    for (int mt = warp; mt < ntiles; mt += 8) {
        int m0 = mt * 16;

        uint32_t q_addr = sb + SM_QH + (m0 + lr + (seg & 1) * 8) * 144 + (seg >> 1) * 16;
        uint32_t aq[4][4];
#pragma unroll
        for (int ks = 0; ks < 4; ks++)
            LDSM_X4(aq[ks][0], aq[ks][1], aq[ks][2], aq[ks][3], q_addr + ks * 32);

        uint32_t k_addr = sb + SM_KH + lr * 144 + (seg & 1) * 16;
        float s[20][4];
#pragma unroll
        for (int nf = 0; nf < 20; nf++) {
            s[nf][0] = 0.f; s[nf][1] = 0.f; s[nf][2] = 0.f; s[nf][3] = 0.f;
        }
#pragma unroll
        for (int nf = 0; nf < 20; nf++) {
            if (nf >= nfc) continue;
            uint32_t ka = k_addr + nf * (8 * 144);
#pragma unroll
            for (int ks = 0; ks < 4; ks++) {
                uint32_t bf[2];
                LDSM_X2(bf[0], bf[1], ka + ks * 32);
                mma_f16(s[nf], aq[ks], bf);
            }
        }

        float mx0 = -1e30f, mx1 = -1e30f;
#pragma unroll
        for (int nf = 0; nf < 20; nf++) {
            if (nf >= nfc) continue;
            int col0 = nf * 8 + 2 * c;
            s[nf][0] = (col0     < n) ? s[nf][0] * 0.125f : -1e30f;
            s[nf][1] = (col0 + 1 < n) ? s[nf][1] * 0.125f : -1e30f;
            s[nf][2] = (col0     < n) ? s[nf][2] * 0.125f : -1e30f;
            s[nf][3] = (col0 + 1 < n) ? s[nf][3] * 0.125f : -1e30f;
            mx0 = fmaxf(mx0, fmaxf(s[nf][0], s[nf][1]));
            mx1 = fmaxf(mx1, fmaxf(s[nf][2], s[nf][3]));
        }
        mx0 = fmaxf(mx0, __shfl_xor_sync(0xffffffffu, mx0, 1));
        mx0 = fmaxf(mx0, __shfl_xor_sync(0xffffffffu, mx0, 2));
        mx1 = fmaxf(mx1, __shfl_xor_sync(0xffffffffu, mx1, 1));
        mx1 = fmaxf(mx1, __shfl_xor_sync(0xffffffffu, mx1, 2));

        float sum0 = 0.f, sum1 = 0.f;
#pragma unroll
        for (int nf = 0; nf < 20; nf++) {
            if (nf >= nfc) continue;
            float p0 = __expf(s[nf][0] - mx0);
            float p1 = __expf(s[nf][1] - mx0);
            float p2 = __expf(s[nf][2] - mx1);
            float p3 = __expf(s[nf][3] - mx1);
            s[nf][0] = p0; s[nf][1] = p1; s[nf][2] = p2; s[nf][3] = p3;
            sum0 += p0 + p1;
            sum1 += p2 + p3;
        }
        sum0 += __shfl_xor_sync(0xffffffffu, sum0, 1);
        sum0 += __shfl_xor_sync(0xffffffffu, sum0, 2);
        sum1 += __shfl_xor_sync(0xffffffffu, sum1, 1);
        sum1 += __shfl_xor_sync(0xffffffffu, sum1, 2);
        float inv0 = 1.f / sum0;
        float inv1 = 1.f / sum1;

        // ---- O = P V (P packed from S regs, V via ldmatrix.trans) ----
        uint32_t v_base = sb + SM_V + (lane & 15) * 144;
        float o[8][4];
#pragma unroll
        for (int nd = 0; nd < 8; nd++) {
            o[nd][0] = 0.f; o[nd][1] = 0.f; o[nd][2] = 0.f; o[nd][3] = 0.f;
        }
#pragma unroll
        for (int ks = 0; ks < 10; ks++) {
            if (ks >= ntiles) continue;
            __half2 h0 = __floats2half2_rn(s[2 * ks][0],     s[2 * ks][1]);
            __half2 h1 = __floats2half2_rn(s[2 * ks][2],     s[2 * ks][3]);
            __half2 h2v = __floats2half2_rn(s[2 * ks + 1][0], s[2 * ks + 1][1]);
            __half2 h3 = __floats2half2_rn(s[2 * ks + 1][2], s[2 * ks + 1][3]);
            uint32_t ap[4];
            ap[0] = *(uint32_t*)&h0;
            ap[1] = *(uint32_t*)&h1;
            ap[2] = *(uint32_t*)&h2v;
            ap[3] = *(uint32_t*)&h3;
            uint32_t va = v_base + ks * 2304;   // 16 rows * 144 B
#pragma unroll
            for (int nd = 0; nd < 8; nd++) {
                uint32_t bf[2];
                LDSM_X2T(bf[0], bf[1], va + nd * 16);
                mma_f16(o[nd], ap, bf);
            }
        }

        int row0 = m0 + r, row1 = m0 + r + 8;
        if (POOL) {
            float* pg = pooled + g * DMODEL + h * DHEAD;
#pragma unroll
            for (int nd = 0; nd < 8; nd++) {
                float v0 = (row0 < n ? o[nd][0] * inv0 : 0.f) + (row1 < n ? o[nd][2] * inv1 : 0.f);
                float v1 = (row0 < n ? o[nd][1] * inv0 : 0.f) + (row1 < n ? o[nd][3] * inv1 : 0.f);
                v0 += __shfl_xor_sync(0xffffffffu, v0, 4);
                v1 += __shfl_xor_sync(0xffffffffu, v1, 4);
                v0 += __shfl_xor_sync(0xffffffffu, v0, 8);
                v1 += __shfl_xor_sync(0xffffffffu, v1, 8);
                v0 += __shfl_xor_sync(0xffffffffu, v0, 16);
                v1 += __shfl_xor_sync(0xffffffffu, v1, 16);
                if (r == 0) {
                    atomicAdd(pg + nd * 8 + 2 * c,     v0);
                    atomicAdd(pg + nd * 8 + 2 * c + 1, v1);
                }
            }
        } else {
#pragma unroll
            for (int nd = 0; nd < 8; nd++) {
                int col = h * DHEAD + nd * 8 + 2 * c;
                if (row0 < n)
                    *(__half2*)(out + (size_t)(s0 + row0) * DMODEL + col) =
                        __floats2half2_rn(o[nd][0] * inv0, o[nd][1] * inv0);
                if (row1 < n)
                    *(__half2*)(out + (size_t)(s0 + row1) * DMODEL + col) =
                        __floats2half2_rn(o[nd][2] * inv1, o[nd][3] * inv1);
            }
        }
        __syncwarp();
    }
}

// ======== fused readout: mean, out_proj2, MLP, final dot (1 CTA/graph) ====
__global__ void __launch_bounds__(256)
readout_kernel(const float* __restrict__ ps,
               const float* __restrict__ wo2, const float* __restrict__ bo2,
               const float* __restrict__ w1,  const float* __restrict__ b1,
               const float* __restrict__ w2,  const float* __restrict__ b2,
               const float* __restrict__ w3,  const float* __restrict__ b3,
               float* __restrict__ out) {
    __shared__ float bA[256], bB[256];
    __shared__ float red[8];
    int g = blockIdx.x, t = threadIdx.x, lane = t & 31, warp = t >> 5;
    int n = g_start[g + 1] - g_start[g];
    bA[t] = ps[g * DMODEL + t] / (float)n;
    __syncthreads();

    // pooled2 = Wo2 @ mean + bo2
#pragma unroll 1
    for (int row = warp * 32; row < warp * 32 + 32; row++) {
        float a = 0.f;
#pragma unroll
        for (int kk = 0; kk < 8; kk++)
            a += wo2[row * DMODEL + kk * 32 + lane] * bA[kk * 32 + lane];
#pragma unroll
        for (int o = 16; o; o >>= 1) a += __shfl_xor_sync(0xffffffffu, a, o);
        if (lane == 0) bB[row] = a + bo2[row];
    }
    __syncthreads();

    // r1 = relu(W1 @ pooled2 + b1)
#pragma unroll 1
    for (int row = warp * 32; row < warp * 32 + 32; row++) {
        float a = 0.f;
#pragma unroll
        for (int kk = 0; kk < 8; kk++)
            a += w1[row * DMODEL + kk * 32 + lane] * bB[kk * 32 + lane];
#pragma unroll
        for (int o = 16; o; o >>= 1) a += __shfl_xor_sync(0xffffffffu, a, o);
        if (lane == 0) bA[row] = fmaxf(a + b1[row], 0.f);
    }
    __syncthreads();

    // r2 = relu(W2 @ r1 + b2), 128 rows
    if (warp < 4) {
#pragma unroll 1
        for (int row = warp * 32; row < warp * 32 + 32; row++) {
            float a = 0.f;
#pragma unroll
            for (int kk = 0; kk < 8; kk++)
                a += w2[row * DMODEL + kk * 32 + lane] * bA[kk * 32 + lane];
#pragma unroll
            for (int o = 16; o; o >>= 1) a += __shfl_xor_sync(0xffffffffu, a, o);
            if (lane == 0) bB[row] = fmaxf(a + b2[row], 0.f);
        }
    }
    __syncthreads();

    // energy = dot(w3, r2) + b3
    float v = (t < 128) ? bB[t] * w3[t] : 0.f;
#pragma unroll
    for (int o = 16; o; o >>= 1) v += __shfl_xor_sync(0xffffffffu, v, o);
    if (lane == 0) red[warp] = v;
    __syncthreads();
    if (t == 0)
        out[g] = red[0] + red[1] + red[2] + red[3] +
                 red[4] + red[5] + red[6] + red[7] + b3[0];
}

// ---------------- launch ----------------
extern "C" void kernel_launch(void* const* d_in, const int* in_sizes, int n_in,
                              void* d_out, int out_size) {
    const float* x      = (const float*)d_in[0];
    const int*   batch  = (const int*)  d_in[1];
    const float* in_w1  = (const float*)d_in[2];
    const float* in_b1  = (const float*)d_in[3];
    const float* out_w1 = (const float*)d_in[4];
    const float* out_b1 = (const float*)d_in[5];
    const float* in_w2  = (const float*)d_in[6];
    const float* in_b2  = (const float*)d_in[7];
    const float* out_w2 = (const float*)d_in[8];
    const float* out_b2 = (const float*)d_in[9];
    const float* r_w1   = (const float*)d_in[10];
    const float* r_b1   = (const float*)d_in[11];
    const float* r_w2   = (const float*)d_in[12];
    const float* r_b2   = (const float*)d_in[13];
    const float* r_w3   = (const float*)d_in[14];
    const float* r_b3   = (const float*)d_in[15];
    float* out = (float*)d_out;

    __half *qkv, *bufA, *xh, *w1h, *w2h, *wo1t, *wcomb;
    float *pooled, *bcomb, *zero256;
    cudaGetSymbolAddress((void**)&qkv,    g_qkv);
    cudaGetSymbolAddress((void**)&bufA,   g_bufA);
    cudaGetSymbolAddress((void**)&xh,     g_xh);
    cudaGetSymbolAddress((void**)&w1h,    g_w1h);
    cudaGetSymbolAddress((void**)&w2h,    g_w2h);
    cudaGetSymbolAddress((void**)&wo1t,   g_wo1t);
    cudaGetSymbolAddress((void**)&wcomb,  g_wcomb);
    cudaGetSymbolAddress((void**)&bcomb,  g_bcomb);
    cudaGetSymbolAddress((void**)&zero256, g_zero256);
    cudaGetSymbolAddress((void**)&pooled, g_pooled);

    cudaFuncSetAttribute(attention_tc_kernel<false>,
                         cudaFuncAttributeMaxDynamicSharedMemorySize, ATTN_SMEM7);
    cudaFuncSetAttribute(attention_tc_kernel<true>,
                         cudaFuncAttributeMaxDynamicSharedMemorySize, ATTN_SMEM7);
    cudaFuncSetAttribute(h16_gemm_kernel,
                         cudaFuncAttributeMaxDynamicSharedMemorySize, TCG_SMEM);

    compute_starts_kernel<<<(TOTAL_ATOMS + 255) / 256, 256>>>(batch);

    int totF4 = NX4 + 2 * NW4 + NP4;
    f2h_all_kernel<<<(totF4 + 255) / 256, 256>>>(x, in_w1, in_w2, xh, w1h, w2h, pooled);

    // ---- precompute fused layer weights ----
    dim3 tgrid(8, 8), tblk(32, 32);
    transpose_h_kernel<<<tgrid, tblk>>>(out_w1, wo1t);
    dim3 gPC(2, 6);
    h16_gemm_kernel<<<gPC, 256, TCG_SMEM>>>(w2h, wo1t, zero256, wcomb, DMODEL);
    bcomb_kernel<<<3 * DMODEL, 128>>>(in_w2, out_b1, in_b2, bcomb);

    dim3 gQKV(3 * DMODEL / 128, TOTAL_ATOMS / 128);
    dim3 gATT(NUM_GRAPHS, NHEAD);

    // layer 1: in_proj + attention
    h16_gemm_kernel<<<gQKV, 256, TCG_SMEM>>>(xh, w1h, in_b1, qkv, 3 * DMODEL);
    attention_tc_kernel<false><<<gATT, 256, ATTN_SMEM7>>>(qkv, bufA, pooled);

    // fused out_proj(L1) + in_proj(L2)
    h16_gemm_kernel<<<gQKV, 256, TCG_SMEM>>>(bufA, wcomb, bcomb, qkv, 3 * DMODEL);
    // attention 2 with fused mean-pool accumulation
    attention_tc_kernel<true><<<gATT, 256, ATTN_SMEM7>>>(qkv, bufA, pooled);

    // fused readout (mean + out_proj2 + MLP + final)
    readout_kernel<<<NUM_GRAPHS, 256>>>(pooled, out_w2, out_b2,
                                        r_w1, r_b1, r_w2, r_b2, r_w3, r_b3, out);
}